// round 9
// baseline (speedup 1.0000x reference)
#include <cuda_runtime.h>
#include <math.h>

// ---------------- problem constants ----------------
#define NN      512
#define LIN     640
#define LEADS   3
#define T1      322
#define T2      161
#define T3      79
#define C1      64
#define C2      128
#define C3      256
#define ER      648     // ecgT padded rows (pad 4 each side)
#define X1R     336     // x1 padded rows (valid p=3..324)
#define X2R     168     // x2 padded rows (valid p=2..162)
#define FLAT    20224
#define NUMK    100
#define DIMK    5
#define ACTW    500
#define GKS     8
#define GKC     2528    // 20224/8
#define GWB     158     // weight-stage rows; 2528 = 16*158
#define FCH     64
#define FPERC   316     // 64*316 = 20224

// ---------------- device scratch (n-major layouts) ----------------
__device__ float g_inv_sigma[3];
__device__ float g_w1t[15 * C1];        // (ik, oc)
__device__ float g_w2t[448 * C2];
__device__ float g_w3t[1152 * C3];
__device__ float g_ecgT[LEADS * ER * NN];       // [lead][p][n]
__device__ float g_x1[C1 * X1R * NN];           // [ic][p][n]
__device__ float g_x2[C2 * X2R * NN];
__device__ float g_flat[FLAT * NN];             // [f][n], f = oc*79+t
__device__ float g_act_part[GKS * ACTW * NN];
__device__ float g_act[ACTW * NN];              // [j][n]
__device__ float g_feats[NUMK * NN];            // [m][n]
__device__ float g_fpart[FCH * NN];

typedef unsigned long long ull;

__device__ __forceinline__ void ffma2(ull& d, const ull a, const ull b) {
    asm("fma.rn.f32x2 %0, %1, %2, %0;" : "+l"(d) : "l"(a), "l"(b));
}
__device__ __forceinline__ ull add2(const ull a, const ull b) {
    ull d; asm("add.rn.f32x2 %0, %1, %2;" : "=l"(d) : "l"(a), "l"(b)); return d;
}
__device__ __forceinline__ ull abs2(const ull a) {
    return a & 0x7FFFFFFF7FFFFFFFULL;
}
__device__ __forceinline__ ull pack2(float x, float y) {
    ull u; asm("mov.b64 %0, {%1,%2};" : "=l"(u) : "f"(x), "f"(y)); return u;
}
__device__ __forceinline__ float2 unpack(ull u) {
    float2 f; asm("mov.b64 {%0,%1}, %2;" : "=f"(f.x), "=f"(f.y) : "l"(u)); return f;
}
__device__ __forceinline__ float leaky(float x) { return x >= 0.f ? x : 0.2f * x; }

// ---------------- spectral norm ----------------
__global__ void sigma_k(const float* __restrict__ w1, const float* __restrict__ u1,
                        const float* __restrict__ w2, const float* __restrict__ u2,
                        const float* __restrict__ w3, const float* __restrict__ u3) {
    const float* W; const float* U; int O, IK;
    if (blockIdx.x == 0)      { W = w1; U = u1; O = C1; IK = 15;   }
    else if (blockIdx.x == 1) { W = w2; U = u2; O = C2; IK = 448;  }
    else                      { W = w3; U = u3; O = C3; IK = 1152; }

    __shared__ float sv[1152];
    __shared__ float red[256];
    int tid = threadIdx.x;

    float local = 0.f;
    for (int j = tid; j < IK; j += 256) {
        float v = 0.f;
        for (int i = 0; i < O; i++) v += W[i * IK + j] * U[i];
        sv[j] = v;
        local += v * v;
    }
    red[tid] = local; __syncthreads();
    for (int s = 128; s > 0; s >>= 1) { if (tid < s) red[tid] += red[tid + s]; __syncthreads(); }
    float vscale = 1.f / (sqrtf(red[0]) + 1e-12f);
    __syncthreads();
    for (int j = tid; j < IK; j += 256) sv[j] *= vscale;
    __syncthreads();

    float local2 = 0.f;
    for (int i = tid; i < O; i += 256) {
        float t = 0.f;
        for (int j = 0; j < IK; j++) t += W[i * IK + j] * sv[j];
        local2 += t * t;
    }
    red[tid] = local2; __syncthreads();
    for (int s = 128; s > 0; s >>= 1) { if (tid < s) red[tid] += red[tid + s]; __syncthreads(); }
    if (tid == 0) {
        float nt = red[0];
        float sigma = nt / (sqrtf(nt) + 1e-12f);
        g_inv_sigma[blockIdx.x] = 1.f / sigma;
    }
}

// ---------------- weight transpose + scale ----------------
__global__ void wprep_k(const float* __restrict__ w1, const float* __restrict__ w2,
                        const float* __restrict__ w3) {
    int idx = blockIdx.x * 256 + threadIdx.x;
    if (idx < 1152 * C3) {
        int oc = idx % C3, r = idx / C3;
        g_w3t[idx] = w3[oc * 1152 + r] * g_inv_sigma[2];
    }
    if (idx < 448 * C2) {
        int oc = idx % C2, r = idx / C2;
        g_w2t[idx] = w2[oc * 448 + r] * g_inv_sigma[1];
    }
    if (idx < 15 * C1) {
        int oc = idx % C1, r = idx / C1;
        g_w1t[idx] = w1[oc * 15 + r] * g_inv_sigma[0];
    }
}

// ---------------- transpose ecg(N,L,3) -> ecgT[lead][p][n] ----------------
__global__ void ecgT_k(const float* __restrict__ ecg) {
    int idx = blockIdx.x * 256 + threadIdx.x;
    if (idx >= LEADS * ER * NN) return;
    int n = idx & (NN - 1);
    int rem = idx >> 9;
    int p = rem % ER;
    int lead = rem / ER;
    int t = p - 4;
    g_ecgT[idx] = (t >= 0 && t < LIN) ? ecg[(size_t)n * (LIN * LEADS) + t * LEADS + lead] : 0.f;
}

// ---------------- conv1: ecgT -> x1, k=5 s=2 p=4 (unchanged mapping; small) ----------------
__global__ void conv1_k(const float* __restrict__ b1) {
    __shared__ __align__(16) ull sw[15 * 16];
    int tid = threadIdx.x;                 // 256
    int t0 = blockIdx.x * 2;
    int oc0 = blockIdx.y * 16;
    for (int i = tid; i < 15 * 16; i += 256) {
        int j = i & 15, r = i >> 4;
        float w = g_w1t[r * C1 + oc0 + j];
        sw[i] = pack2(w, w);
    }
    ull acc[16][2];
    #pragma unroll
    for (int j = 0; j < 16; j++) { float b = b1[oc0 + j]; acc[j][0] = acc[j][1] = pack2(b, b); }
    __syncthreads();
    #pragma unroll
    for (int lead = 0; lead < LEADS; lead++) {
        const ull* xp = reinterpret_cast<const ull*>(g_ecgT + ((size_t)lead * ER + 2 * t0) * NN) + tid;
        ull in[7];
        #pragma unroll
        for (int r = 0; r < 7; r++) in[r] = __ldg(xp + r * (NN / 2));
        #pragma unroll
        for (int k = 0; k < 5; k++) {
            #pragma unroll
            for (int jh = 0; jh < 8; jh++) {
                const ulonglong2* wp = reinterpret_cast<const ulonglong2*>(&sw[(lead * 5 + k) * 16 + 2 * jh]);
                ulonglong2 w2 = wp[0];
                ffma2(acc[2 * jh][0],     in[k],     w2.x);
                ffma2(acc[2 * jh][1],     in[k + 2], w2.x);
                ffma2(acc[2 * jh + 1][0], in[k],     w2.y);
                ffma2(acc[2 * jh + 1][1], in[k + 2], w2.y);
            }
        }
    }
    #pragma unroll
    for (int j = 0; j < 16; j++) {
        int oc = oc0 + j;
        float2 v0 = unpack(acc[j][0]);
        float2 v1 = unpack(acc[j][1]);
        v0.x = leaky(v0.x); v0.y = leaky(v0.y);
        v1.x = leaky(v1.x); v1.y = leaky(v1.y);
        float2* o = reinterpret_cast<float2*>(g_x1 + ((size_t)oc * X1R + (t0 + 3)) * NN);
        o[tid] = v0;
        o[NN / 2 + tid] = v1;
    }
}

// ---------------- conv2: x1 -> x2, k=7 s=2 p=3; 4 oc x 2 t x 2 n per thread ----------------
__global__ __launch_bounds__(256, 4) void conv2_k(const float* __restrict__ b2) {
    __shared__ __align__(16) ull sw[32 * 7 * 16]; // 28.7 KB
    int tid = threadIdx.x;
    int ocq = tid >> 6, np = tid & 63;
    int t0 = blockIdx.x * 2;
    int oc0 = blockIdx.y * 16;
    int nb  = blockIdx.z;                  // 0..3 (128 n each)
    bool has_t1 = (t0 + 1) < T2;
    int myoc = oc0 + ocq * 4;
    ull acc[4][2];
    #pragma unroll
    for (int j = 0; j < 4; j++) { float b = b2[myoc + j]; acc[j][0] = acc[j][1] = pack2(b, b); }

    const ull* xb = reinterpret_cast<const ull*>(g_x1) + (size_t)2 * t0 * (NN / 2) + nb * 64 + np;

    for (int ch = 0; ch < 2; ch++) {
        int ic0 = ch * 32;
        __syncthreads();
        for (int i = tid; i < 32 * 7 * 16; i += 256) {
            int j = i & 15, row = i >> 4;
            float w = g_w2t[(ic0 * 7 + row) * C2 + oc0 + j];
            sw[i] = pack2(w, w);
        }
        __syncthreads();
        #pragma unroll 1
        for (int icl = 0; icl < 32; icl++) {
            const ull* xp = xb + (size_t)(ic0 + icl) * X1R * (NN / 2);
            ull in[9];
            #pragma unroll
            for (int r = 0; r < 9; r++) in[r] = __ldg(xp + r * (NN / 2));
            #pragma unroll
            for (int k = 0; k < 7; k++) {
                const ulonglong2* wp = reinterpret_cast<const ulonglong2*>(&sw[(icl * 7 + k) * 16 + ocq * 4]);
                ulonglong2 wa = wp[0], wb = wp[1];
                ffma2(acc[0][0], in[k], wa.x);  ffma2(acc[0][1], in[k + 2], wa.x);
                ffma2(acc[1][0], in[k], wa.y);  ffma2(acc[1][1], in[k + 2], wa.y);
                ffma2(acc[2][0], in[k], wb.x);  ffma2(acc[2][1], in[k + 2], wb.x);
                ffma2(acc[3][0], in[k], wb.y);  ffma2(acc[3][1], in[k + 2], wb.y);
            }
        }
    }
    #pragma unroll
    for (int j = 0; j < 4; j++) {
        int oc = myoc + j;
        float2 v0 = unpack(acc[j][0]);
        float2 v1 = unpack(acc[j][1]);
        v0.x = leaky(v0.x); v0.y = leaky(v0.y);
        v1.x = leaky(v1.x); v1.y = leaky(v1.y);
        float2* o = reinterpret_cast<float2*>(g_x2 + ((size_t)oc * X2R + (t0 + 2)) * NN) + nb * 64 + np;
        o[0] = v0;
        if (has_t1) o[NN / 2] = v1;
    }
}

// ---------------- conv3: x2 -> flat, k=9 s=2 p=2; 4 oc x 2 t x 2 n per thread ----------------
__global__ __launch_bounds__(256, 4) void conv3_k(const float* __restrict__ b3) {
    __shared__ __align__(16) ull sw[32 * 9 * 16]; // 36.9 KB
    int tid = threadIdx.x;
    int ocq = tid >> 6, np = tid & 63;
    int t0 = blockIdx.x * 2;
    int oc0 = blockIdx.y * 16;
    int nb  = blockIdx.z;                  // 0..3
    bool has_t1 = (t0 + 1) < T3;
    int myoc = oc0 + ocq * 4;
    ull acc[4][2];
    #pragma unroll
    for (int j = 0; j < 4; j++) { float b = b3[myoc + j]; acc[j][0] = acc[j][1] = pack2(b, b); }

    const ull* xb = reinterpret_cast<const ull*>(g_x2) + (size_t)2 * t0 * (NN / 2) + nb * 64 + np;

    for (int ch = 0; ch < 4; ch++) {
        int ic0 = ch * 32;
        __syncthreads();
        for (int i = tid; i < 32 * 9 * 16; i += 256) {
            int j = i & 15, row = i >> 4;
            float w = g_w3t[(ic0 * 9 + row) * C3 + oc0 + j];
            sw[i] = pack2(w, w);
        }
        __syncthreads();
        #pragma unroll 1
        for (int icl = 0; icl < 32; icl++) {
            const ull* xp = xb + (size_t)(ic0 + icl) * X2R * (NN / 2);
            ull in[11];
            #pragma unroll
            for (int r = 0; r < 11; r++) in[r] = __ldg(xp + r * (NN / 2));
            #pragma unroll
            for (int k = 0; k < 9; k++) {
                const ulonglong2* wp = reinterpret_cast<const ulonglong2*>(&sw[(icl * 9 + k) * 16 + ocq * 4]);
                ulonglong2 wa = wp[0], wb = wp[1];
                ffma2(acc[0][0], in[k], wa.x);  ffma2(acc[0][1], in[k + 2], wa.x);
                ffma2(acc[1][0], in[k], wa.y);  ffma2(acc[1][1], in[k + 2], wa.y);
                ffma2(acc[2][0], in[k], wb.x);  ffma2(acc[2][1], in[k + 2], wb.x);
                ffma2(acc[3][0], in[k], wb.y);  ffma2(acc[3][1], in[k + 2], wb.y);
            }
        }
    }
    #pragma unroll
    for (int j = 0; j < 4; j++) {
        int oc = myoc + j;
        float2 v0 = unpack(acc[j][0]);
        float2 v1 = unpack(acc[j][1]);
        v0.x = leaky(v0.x); v0.y = leaky(v0.y);
        v1.x = leaky(v1.x); v1.y = leaky(v1.y);
        float2* o = reinterpret_cast<float2*>(g_flat + ((size_t)oc * T3 + t0) * NN) + nb * 64 + np;
        o[0] = v0;
        if (has_t1) o[NN / 2] = v1;
    }
}

// ---------------- GEMM: act[j][n] = sum_f mb_w[f][j] * flat[f][n]; 4 j x 4 n / thread ----------------
__global__ __launch_bounds__(256) void gemm_k(const float* __restrict__ mbw) {
    __shared__ __align__(16) ull sw[GWB * 16];   // 20.2 KB
    int tid = threadIdx.x;
    int jq = tid >> 6, np = tid & 63;
    int j0 = blockIdx.x * 16;
    int nb = blockIdx.y;               // 0..1 (256 n each)
    int kz = blockIdx.z;               // 0..7
    int f_begin = kz * GKC, f_end = f_begin + GKC;
    int off = nb * 64 + np;            // ulonglong2 index within a 128-wide row
    ull acc[4][2];
    #pragma unroll
    for (int j = 0; j < 4; j++) acc[j][0] = acc[j][1] = 0ULL;

    const ulonglong2* fb = reinterpret_cast<const ulonglong2*>(g_flat);
    ulonglong2 abuf[2];
    abuf[0] = __ldg(fb + (size_t)f_begin * (NN / 4) + off);
    abuf[1] = __ldg(fb + (size_t)(f_begin + 1) * (NN / 4) + off);

    for (int f0 = f_begin; f0 < f_end; f0 += GWB) {
        __syncthreads();
        for (int i = tid; i < GWB * 16; i += 256) {
            int j = i & 15, r = i >> 4;
            int col = j0 + j;
            float w = (col < ACTW) ? mbw[(size_t)(f0 + r) * ACTW + col] : 0.f;
            sw[i] = pack2(w, w);
        }
        __syncthreads();
        #pragma unroll 2
        for (int r = 0; r < GWB; r++) {
            ulonglong2 av = abuf[r & 1];
            int fpre = f0 + r + 2;
            if (fpre < f_end) abuf[r & 1] = __ldg(fb + (size_t)fpre * (NN / 4) + off);
            const ulonglong2* wp = reinterpret_cast<const ulonglong2*>(&sw[r * 16 + jq * 4]);
            ulonglong2 wa = wp[0], wb = wp[1];
            ffma2(acc[0][0], av.x, wa.x); ffma2(acc[0][1], av.y, wa.x);
            ffma2(acc[1][0], av.x, wa.y); ffma2(acc[1][1], av.y, wa.y);
            ffma2(acc[2][0], av.x, wb.x); ffma2(acc[2][1], av.y, wb.x);
            ffma2(acc[3][0], av.x, wb.y); ffma2(acc[3][1], av.y, wb.y);
        }
    }
    #pragma unroll
    for (int jl = 0; jl < 4; jl++) {
        int col = j0 + jq * 4 + jl;
        if (col < ACTW) {
            float2 v0 = unpack(acc[jl][0]), v1 = unpack(acc[jl][1]);
            float4 v = make_float4(v0.x, v0.y, v1.x, v1.y);
            *reinterpret_cast<float4*>(g_act_part + ((size_t)kz * ACTW + col) * NN + (size_t)off * 4) = v;
        }
    }
}

__global__ void kreduce_k() {
    int idx = blockIdx.x * 256 + threadIdx.x;
    if (idx < ACTW * NN) {
        float s = 0.f;
        #pragma unroll
        for (int z = 0; z < GKS; z++) s += g_act_part[(size_t)z * (ACTW * NN) + idx];
        g_act[idx] = s;
    }
}

// ---------------- minibatch discrimination (f32x2 over j-pairs) ----------------
__global__ void mbfeat_k() {
    __shared__ ull sb[DIMK][NN / 2];       // negated pairs {-act[2p], -act[2p+1]}
    int m = blockIdx.x, tid = threadIdx.x; // 512 threads
    float a[DIMK];
    #pragma unroll
    for (int d = 0; d < DIMK; d++)
        a[d] = g_act[(size_t)(m * DIMK + d) * NN + tid];
    for (int i = tid; i < DIMK * (NN / 2); i += NN) {
        int d = i / (NN / 2), p = i % (NN / 2);
        const float* src = g_act + (size_t)(m * DIMK + d) * NN + 2 * p;
        sb[d][p] = pack2(-src[0], -src[1]);
    }
    __syncthreads();
    ull ad[DIMK];
    #pragma unroll
    for (int d = 0; d < DIMK; d++) ad[d] = pack2(a[d], a[d]);
    float s = 0.f;
    for (int p = 0; p < NN / 2; p++) {
        ull l = abs2(add2(ad[0], sb[0][p]));
        #pragma unroll
        for (int d = 1; d < DIMK; d++)
            l = add2(l, abs2(add2(ad[d], sb[d][p])));
        float2 lf = unpack(l);
        s += __expf(-lf.x) + __expf(-lf.y);
    }
    g_feats[(size_t)m * NN + tid] = s;
}

// ---------------- final dot: partial over f-chunks, then reduce ----------------
__global__ void final_part_k(const float* __restrict__ fc_w) {
    int tid = threadIdx.x;                 // 256 (n-pairs)
    int base = blockIdx.x * FPERC;
    ull s2 = 0ULL;
    const ull* fb = reinterpret_cast<const ull*>(g_flat);
    #pragma unroll 4
    for (int r = 0; r < FPERC; r++) {
        int f = base + r;
        float w = __ldg(fc_w + f);
        ffma2(s2, __ldg(fb + (size_t)f * (NN / 2) + tid), pack2(w, w));
    }
    float2 v = unpack(s2);
    reinterpret_cast<float2*>(g_fpart + (size_t)blockIdx.x * NN)[tid] = v;
}

__global__ void final_red_k(const int* __restrict__ condition, const float* __restrict__ emb,
                            const float* __restrict__ cond_w, const float* __restrict__ cond_b,
                            const float* __restrict__ fc_w, const float* __restrict__ fc_b,
                            float* __restrict__ out) {
    int n = threadIdx.x;                   // 512
    float s = fc_b[0];
    for (int b = 0; b < FCH; b++) s += g_fpart[(size_t)b * NN + n];
    for (int m = 0; m < NUMK; m++) s += g_feats[(size_t)m * NN + n] * fc_w[FLAT + m];
    float e = emb[condition[n]];
    for (int i = 0; i < 50; i++) s += (e * cond_w[i] + cond_b[i]) * fc_w[FLAT + NUMK + i];
    out[n] = s;
}

// ---------------- launch ----------------
extern "C" void kernel_launch(void* const* d_in, const int* in_sizes, int n_in,
                              void* d_out, int out_size) {
    const float* ecg       = (const float*)d_in[0];
    const int*   condition = (const int*)  d_in[1];
    const float* w1        = (const float*)d_in[2];
    const float* b1        = (const float*)d_in[3];
    const float* u1        = (const float*)d_in[4];
    const float* w2        = (const float*)d_in[5];
    const float* b2        = (const float*)d_in[6];
    const float* u2        = (const float*)d_in[7];
    const float* w3        = (const float*)d_in[8];
    const float* b3        = (const float*)d_in[9];
    const float* u3        = (const float*)d_in[10];
    const float* emb       = (const float*)d_in[11];
    const float* cond_w    = (const float*)d_in[12];
    const float* cond_b    = (const float*)d_in[13];
    const float* mb_w      = (const float*)d_in[14];
    const float* fc_w      = (const float*)d_in[15];
    const float* fc_b      = (const float*)d_in[16];
    float* out = (float*)d_out;

    sigma_k<<<3, 256>>>(w1, u1, w2, u2, w3, u3);
    wprep_k<<<(1152 * C3 + 255) / 256, 256>>>(w1, w2, w3);
    ecgT_k<<<(LEADS * ER * NN + 255) / 256, 256>>>(ecg);
    conv1_k<<<dim3(T1 / 2, C1 / 16), 256>>>(b1);
    conv2_k<<<dim3((T2 + 1) / 2, C2 / 16, 4), 256>>>(b2);
    conv3_k<<<dim3((T3 + 1) / 2, C3 / 16, 4), 256>>>(b3);
    gemm_k<<<dim3((ACTW + 15) / 16, 2, GKS), 256>>>(mb_w);
    kreduce_k<<<(ACTW * NN + 255) / 256, 256>>>();
    mbfeat_k<<<NUMK, NN>>>();
    final_part_k<<<FCH, 256>>>(fc_w);
    final_red_k<<<1, NN>>>(condition, emb, cond_w, cond_b, fc_w, fc_b, out);
}

// round 11
// speedup vs baseline: 1.1787x; 1.1787x over previous
#include <cuda_runtime.h>
#include <math.h>

// ---------------- problem constants ----------------
#define NN      512
#define LIN     640
#define LEADS   3
#define T1      322
#define T2      161
#define T3      79
#define C1      64
#define C2      128
#define C3      256
#define ER      648     // ecgT padded rows (pad 4 each side)
#define X1R     336     // x1 padded rows (valid p=3..324)
#define X2R     168     // x2 padded rows (valid p=2..162)
#define FLAT    20224
#define NUMK    100
#define DIMK    5
#define ACTW    500
#define GJT     32
#define GKS     32
#define GKC     632     // 20224/32
#define GWB     158     // weight-stage rows; 632 = 4*158
#define FCH     64
#define FPERC   316     // 64*316 = 20224

// ---------------- device scratch (n-major layouts) ----------------
__device__ float g_inv_sigma[3];
__device__ float g_w1t[15 * C1];        // (ik, oc)
__device__ float g_w2t[448 * C2];
__device__ float g_w3t[1152 * C3];
__device__ float g_ecgT[LEADS * ER * NN];       // [lead][p][n]
__device__ float g_x1[C1 * X1R * NN];           // [ic][p][n]
__device__ float g_x2[C2 * X2R * NN];
__device__ float g_flat[FLAT * NN];             // [f][n], f = oc*79+t
__device__ float g_act_part[GKS * ACTW * NN];
__device__ float g_act[ACTW * NN];              // [j][n]
__device__ float g_feats[NUMK * NN];            // [m][n]
__device__ float g_fpart[FCH * NN];

typedef unsigned long long ull;

__device__ __forceinline__ void ffma2(ull& d, const ull a, const ull b) {
    asm("fma.rn.f32x2 %0, %1, %2, %0;" : "+l"(d) : "l"(a), "l"(b));
}
__device__ __forceinline__ ull add2(const ull a, const ull b) {
    ull d; asm("add.rn.f32x2 %0, %1, %2;" : "=l"(d) : "l"(a), "l"(b)); return d;
}
__device__ __forceinline__ ull abs2(const ull a) {
    return a & 0x7FFFFFFF7FFFFFFFULL;
}
__device__ __forceinline__ ull pack2(float x, float y) {
    ull u; asm("mov.b64 %0, {%1,%2};" : "=l"(u) : "f"(x), "f"(y)); return u;
}
__device__ __forceinline__ float2 unpack(ull u) {
    float2 f; asm("mov.b64 {%0,%1}, %2;" : "=f"(f.x), "=f"(f.y) : "l"(u)); return f;
}
__device__ __forceinline__ float leaky(float x) { return x >= 0.f ? x : 0.2f * x; }

// ---------------- spectral norm ----------------
__global__ void sigma_k(const float* __restrict__ w1, const float* __restrict__ u1,
                        const float* __restrict__ w2, const float* __restrict__ u2,
                        const float* __restrict__ w3, const float* __restrict__ u3) {
    const float* W; const float* U; int O, IK;
    if (blockIdx.x == 0)      { W = w1; U = u1; O = C1; IK = 15;   }
    else if (blockIdx.x == 1) { W = w2; U = u2; O = C2; IK = 448;  }
    else                      { W = w3; U = u3; O = C3; IK = 1152; }

    __shared__ float sv[1152];
    __shared__ float red[256];
    int tid = threadIdx.x;

    float local = 0.f;
    for (int j = tid; j < IK; j += 256) {
        float v = 0.f;
        for (int i = 0; i < O; i++) v += W[i * IK + j] * U[i];
        sv[j] = v;
        local += v * v;
    }
    red[tid] = local; __syncthreads();
    for (int s = 128; s > 0; s >>= 1) { if (tid < s) red[tid] += red[tid + s]; __syncthreads(); }
    float vscale = 1.f / (sqrtf(red[0]) + 1e-12f);
    __syncthreads();
    for (int j = tid; j < IK; j += 256) sv[j] *= vscale;
    __syncthreads();

    float local2 = 0.f;
    for (int i = tid; i < O; i += 256) {
        float t = 0.f;
        for (int j = 0; j < IK; j++) t += W[i * IK + j] * sv[j];
        local2 += t * t;
    }
    red[tid] = local2; __syncthreads();
    for (int s = 128; s > 0; s >>= 1) { if (tid < s) red[tid] += red[tid + s]; __syncthreads(); }
    if (tid == 0) {
        float nt = red[0];
        float sigma = nt / (sqrtf(nt) + 1e-12f);
        g_inv_sigma[blockIdx.x] = 1.f / sigma;
    }
}

// ---------------- weight transpose + scale ----------------
__global__ void wprep_k(const float* __restrict__ w1, const float* __restrict__ w2,
                        const float* __restrict__ w3) {
    int idx = blockIdx.x * 256 + threadIdx.x;
    if (idx < 1152 * C3) {
        int oc = idx % C3, r = idx / C3;
        g_w3t[idx] = w3[oc * 1152 + r] * g_inv_sigma[2];
    }
    if (idx < 448 * C2) {
        int oc = idx % C2, r = idx / C2;
        g_w2t[idx] = w2[oc * 448 + r] * g_inv_sigma[1];
    }
    if (idx < 15 * C1) {
        int oc = idx % C1, r = idx / C1;
        g_w1t[idx] = w1[oc * 15 + r] * g_inv_sigma[0];
    }
}

// ---------------- transpose ecg(N,L,3) -> ecgT[lead][p][n] ----------------
__global__ void ecgT_k(const float* __restrict__ ecg) {
    int idx = blockIdx.x * 256 + threadIdx.x;
    if (idx >= LEADS * ER * NN) return;
    int n = idx & (NN - 1);
    int rem = idx >> 9;
    int p = rem % ER;
    int lead = rem / ER;
    int t = p - 4;
    g_ecgT[idx] = (t >= 0 && t < LIN) ? ecg[(size_t)n * (LIN * LEADS) + t * LEADS + lead] : 0.f;
}

// ---------------- conv1: ecgT -> x1, k=5 s=2 p=4; 8 oc x 2 t x 2 n / thread ----------------
__global__ __launch_bounds__(256, 4) void conv1_k(const float* __restrict__ b1) {
    __shared__ __align__(16) ull sw[15 * 8];
    int tid = threadIdx.x;                 // 256 = all 512 n (pairs)
    int t0 = blockIdx.x * 2;
    int oc0 = blockIdx.y * 8;
    for (int i = tid; i < 15 * 8; i += 256) {
        int j = i & 7, r = i >> 3;
        float w = g_w1t[r * C1 + oc0 + j];
        sw[i] = pack2(w, w);
    }
    ull acc[8][2];
    #pragma unroll
    for (int j = 0; j < 8; j++) { float b = b1[oc0 + j]; acc[j][0] = acc[j][1] = pack2(b, b); }
    __syncthreads();
    #pragma unroll
    for (int lead = 0; lead < LEADS; lead++) {
        const ull* xp = reinterpret_cast<const ull*>(g_ecgT + ((size_t)lead * ER + 2 * t0) * NN) + tid;
        ull in[7];
        #pragma unroll
        for (int r = 0; r < 7; r++) in[r] = __ldg(xp + r * (NN / 2));
        #pragma unroll
        for (int k = 0; k < 5; k++) {
            const ulonglong2* wp = reinterpret_cast<const ulonglong2*>(&sw[(lead * 5 + k) * 8]);
            ulonglong2 wa = wp[0], wb = wp[1], wc = wp[2], wd = wp[3];
            ffma2(acc[0][0], in[k], wa.x); ffma2(acc[0][1], in[k + 2], wa.x);
            ffma2(acc[1][0], in[k], wa.y); ffma2(acc[1][1], in[k + 2], wa.y);
            ffma2(acc[2][0], in[k], wb.x); ffma2(acc[2][1], in[k + 2], wb.x);
            ffma2(acc[3][0], in[k], wb.y); ffma2(acc[3][1], in[k + 2], wb.y);
            ffma2(acc[4][0], in[k], wc.x); ffma2(acc[4][1], in[k + 2], wc.x);
            ffma2(acc[5][0], in[k], wc.y); ffma2(acc[5][1], in[k + 2], wc.y);
            ffma2(acc[6][0], in[k], wd.x); ffma2(acc[6][1], in[k + 2], wd.x);
            ffma2(acc[7][0], in[k], wd.y); ffma2(acc[7][1], in[k + 2], wd.y);
        }
    }
    #pragma unroll
    for (int j = 0; j < 8; j++) {
        int oc = oc0 + j;
        float2 v0 = unpack(acc[j][0]);
        float2 v1 = unpack(acc[j][1]);
        v0.x = leaky(v0.x); v0.y = leaky(v0.y);
        v1.x = leaky(v1.x); v1.y = leaky(v1.y);
        float2* o = reinterpret_cast<float2*>(g_x1 + ((size_t)oc * X1R + (t0 + 3)) * NN);
        o[tid] = v0;
        o[NN / 2 + tid] = v1;
    }
}

// ---------------- conv2: x1 -> x2, k=7 s=2 p=3; 8 oc x 2 t x 2 n / thread ----------------
__global__ __launch_bounds__(256, 3) void conv2_k(const float* __restrict__ b2) {
    __shared__ __align__(16) ull sw[64 * 7 * 8];  // 28.7 KB
    int tid = threadIdx.x;
    int t0 = blockIdx.x * 2;
    int oc0 = blockIdx.y * 8;
    bool has_t1 = (t0 + 1) < T2;
    ull acc[8][2];
    #pragma unroll
    for (int j = 0; j < 8; j++) { float b = b2[oc0 + j]; acc[j][0] = acc[j][1] = pack2(b, b); }

    const ull* xb = reinterpret_cast<const ull*>(g_x1) + (size_t)2 * t0 * (NN / 2) + tid;

    // stage all 64 ic of weights once (8 oc slice): 64*7*8 entries
    for (int i = tid; i < 64 * 7 * 8; i += 256) {
        int j = i & 7, row = i >> 3;   // row = ic*7+k
        float w = g_w2t[row * C2 + oc0 + j];
        sw[i] = pack2(w, w);
    }
    __syncthreads();
    #pragma unroll 1
    for (int ic = 0; ic < C1; ic++) {
        const ull* xp = xb + (size_t)ic * X1R * (NN / 2);
        ull in[9];
        #pragma unroll
        for (int r = 0; r < 9; r++) in[r] = __ldg(xp + r * (NN / 2));
        #pragma unroll
        for (int k = 0; k < 7; k++) {
            const ulonglong2* wp = reinterpret_cast<const ulonglong2*>(&sw[(ic * 7 + k) * 8]);
            ulonglong2 wa = wp[0], wb = wp[1], wc = wp[2], wd = wp[3];
            ffma2(acc[0][0], in[k], wa.x); ffma2(acc[0][1], in[k + 2], wa.x);
            ffma2(acc[1][0], in[k], wa.y); ffma2(acc[1][1], in[k + 2], wa.y);
            ffma2(acc[2][0], in[k], wb.x); ffma2(acc[2][1], in[k + 2], wb.x);
            ffma2(acc[3][0], in[k], wb.y); ffma2(acc[3][1], in[k + 2], wb.y);
            ffma2(acc[4][0], in[k], wc.x); ffma2(acc[4][1], in[k + 2], wc.x);
            ffma2(acc[5][0], in[k], wc.y); ffma2(acc[5][1], in[k + 2], wc.y);
            ffma2(acc[6][0], in[k], wd.x); ffma2(acc[6][1], in[k + 2], wd.x);
            ffma2(acc[7][0], in[k], wd.y); ffma2(acc[7][1], in[k + 2], wd.y);
        }
    }
    #pragma unroll
    for (int j = 0; j < 8; j++) {
        int oc = oc0 + j;
        float2 v0 = unpack(acc[j][0]);
        float2 v1 = unpack(acc[j][1]);
        v0.x = leaky(v0.x); v0.y = leaky(v0.y);
        v1.x = leaky(v1.x); v1.y = leaky(v1.y);
        float2* o = reinterpret_cast<float2*>(g_x2 + ((size_t)oc * X2R + (t0 + 2)) * NN);
        o[tid] = v0;
        if (has_t1) o[NN / 2 + tid] = v1;
    }
}

// ---------------- conv3: x2 -> flat, k=9 s=2 p=2; 8 oc x 2 t x 2 n / thread ----------------
__global__ __launch_bounds__(256, 3) void conv3_k(const float* __restrict__ b3) {
    __shared__ __align__(16) ull sw[64 * 9 * 8];  // 36.9 KB (64-ic chunk x 8 oc)
    int tid = threadIdx.x;
    int t0 = blockIdx.x * 2;
    int oc0 = blockIdx.y * 8;
    bool has_t1 = (t0 + 1) < T3;
    ull acc[8][2];
    #pragma unroll
    for (int j = 0; j < 8; j++) { float b = b3[oc0 + j]; acc[j][0] = acc[j][1] = pack2(b, b); }

    const ull* xb = reinterpret_cast<const ull*>(g_x2) + (size_t)2 * t0 * (NN / 2) + tid;

    for (int ch = 0; ch < 2; ch++) {
        int ic0 = ch * 64;
        __syncthreads();
        for (int i = tid; i < 64 * 9 * 8; i += 256) {
            int j = i & 7, row = i >> 3;  // row = icl*9+k
            float w = g_w3t[(ic0 * 9 + row) * C3 + oc0 + j];
            sw[i] = pack2(w, w);
        }
        __syncthreads();
        #pragma unroll 1
        for (int icl = 0; icl < 64; icl++) {
            const ull* xp = xb + (size_t)(ic0 + icl) * X2R * (NN / 2);
            ull in[11];
            #pragma unroll
            for (int r = 0; r < 11; r++) in[r] = __ldg(xp + r * (NN / 2));
            #pragma unroll
            for (int k = 0; k < 9; k++) {
                const ulonglong2* wp = reinterpret_cast<const ulonglong2*>(&sw[(icl * 9 + k) * 8]);
                ulonglong2 wa = wp[0], wb = wp[1], wc = wp[2], wd = wp[3];
                ffma2(acc[0][0], in[k], wa.x); ffma2(acc[0][1], in[k + 2], wa.x);
                ffma2(acc[1][0], in[k], wa.y); ffma2(acc[1][1], in[k + 2], wa.y);
                ffma2(acc[2][0], in[k], wb.x); ffma2(acc[2][1], in[k + 2], wb.x);
                ffma2(acc[3][0], in[k], wb.y); ffma2(acc[3][1], in[k + 2], wb.y);
                ffma2(acc[4][0], in[k], wc.x); ffma2(acc[4][1], in[k + 2], wc.x);
                ffma2(acc[5][0], in[k], wc.y); ffma2(acc[5][1], in[k + 2], wc.y);
                ffma2(acc[6][0], in[k], wd.x); ffma2(acc[6][1], in[k + 2], wd.x);
                ffma2(acc[7][0], in[k], wd.y); ffma2(acc[7][1], in[k + 2], wd.y);
            }
        }
    }
    #pragma unroll
    for (int j = 0; j < 8; j++) {
        int oc = oc0 + j;
        float2 v0 = unpack(acc[j][0]);
        float2 v1 = unpack(acc[j][1]);
        v0.x = leaky(v0.x); v0.y = leaky(v0.y);
        v1.x = leaky(v1.x); v1.y = leaky(v1.y);
        float2* o = reinterpret_cast<float2*>(g_flat + ((size_t)oc * T3 + t0) * NN);
        o[tid] = v0;
        if (has_t1) o[NN / 2 + tid] = v1;
    }
}

// ---------------- GEMM: act[j][n] = sum_f mb_w[f][j] * flat[f][n], split-K, LDS.128 ----------------
__global__ __launch_bounds__(128, 3) void gemm_k(const float* __restrict__ mbw) {
    __shared__ __align__(16) ull sw[GWB * GJT];  // 40.4 KB (158 rows x 32 j)
    int tid = threadIdx.x;                 // 128; each thread covers 4 n
    int j0 = blockIdx.x * GJT;
    int kz = blockIdx.y;
    int f_begin = kz * GKC, f_end = f_begin + GKC;
    ull acc[GJT][2];
    #pragma unroll
    for (int j = 0; j < GJT; j++) acc[j][0] = acc[j][1] = 0ULL;

    const ull* fbase = reinterpret_cast<const ull*>(g_flat);
    ull a0A = __ldg(fbase + (size_t)f_begin * (NN / 2) + 2 * tid);
    ull a1A = __ldg(fbase + (size_t)f_begin * (NN / 2) + 2 * tid + 1);
    ull a0B, a1B;

    for (int f0 = f_begin; f0 < f_end; f0 += GWB) {
        __syncthreads();
        for (int i = tid; i < GWB * GJT / 2; i += 128) {
            int jh = i & 15, r = i >> 4;
            int col = j0 + 2 * jh;
            float wx = (col < ACTW) ? mbw[(size_t)(f0 + r) * ACTW + col] : 0.f;
            float wy = (col + 1 < ACTW) ? mbw[(size_t)(f0 + r) * ACTW + col + 1] : 0.f;
            sw[r * GJT + 2 * jh]     = pack2(wx, wx);
            sw[r * GJT + 2 * jh + 1] = pack2(wy, wy);
        }
        __syncthreads();
        #pragma unroll 1
        for (int r = 0; r < GWB; r += 2) {
            size_t row1 = (size_t)(f0 + r + 1) * (NN / 2) + 2 * tid;
            a0B = __ldg(fbase + row1);
            a1B = __ldg(fbase + row1 + 1);
            #pragma unroll
            for (int jh = 0; jh < 16; jh++) {
                const ulonglong2* wp = reinterpret_cast<const ulonglong2*>(&sw[r * GJT + 2 * jh]);
                ulonglong2 w2 = wp[0];
                ffma2(acc[2 * jh][0],     a0A, w2.x);
                ffma2(acc[2 * jh][1],     a1A, w2.x);
                ffma2(acc[2 * jh + 1][0], a0A, w2.y);
                ffma2(acc[2 * jh + 1][1], a1A, w2.y);
            }
            int fn = f0 + r + 2;
            if (fn < f_end) {
                size_t row2 = (size_t)fn * (NN / 2) + 2 * tid;
                a0A = __ldg(fbase + row2);
                a1A = __ldg(fbase + row2 + 1);
            }
            #pragma unroll
            for (int jh = 0; jh < 16; jh++) {
                const ulonglong2* wp = reinterpret_cast<const ulonglong2*>(&sw[(r + 1) * GJT + 2 * jh]);
                ulonglong2 w2 = wp[0];
                ffma2(acc[2 * jh][0],     a0B, w2.x);
                ffma2(acc[2 * jh][1],     a1B, w2.x);
                ffma2(acc[2 * jh + 1][0], a0B, w2.y);
                ffma2(acc[2 * jh + 1][1], a1B, w2.y);
            }
        }
    }
    for (int j = 0; j < GJT; j++) {
        int col = j0 + j;
        if (col < ACTW) {
            float2* bp = reinterpret_cast<float2*>(g_act_part + ((size_t)kz * ACTW + col) * NN);
            bp[2 * tid]     = unpack(acc[j][0]);
            bp[2 * tid + 1] = unpack(acc[j][1]);
        }
    }
}

__global__ void kreduce_k() {
    int idx = blockIdx.x * 256 + threadIdx.x;
    if (idx < ACTW * NN) {
        float s = 0.f;
        #pragma unroll
        for (int z = 0; z < GKS; z++) s += g_act_part[(size_t)z * (ACTW * NN) + idx];
        g_act[idx] = s;
    }
}

// ---------------- minibatch discrimination (f32x2 over j-pairs) ----------------
__global__ void mbfeat_k() {
    __shared__ ull sb[DIMK][NN / 2];       // negated pairs {-act[2p], -act[2p+1]}
    int m = blockIdx.x, tid = threadIdx.x; // 512 threads
    float a[DIMK];
    #pragma unroll
    for (int d = 0; d < DIMK; d++)
        a[d] = g_act[(size_t)(m * DIMK + d) * NN + tid];
    for (int i = tid; i < DIMK * (NN / 2); i += NN) {
        int d = i / (NN / 2), p = i % (NN / 2);
        const float* src = g_act + (size_t)(m * DIMK + d) * NN + 2 * p;
        sb[d][p] = pack2(-src[0], -src[1]);
    }
    __syncthreads();
    ull ad[DIMK];
    #pragma unroll
    for (int d = 0; d < DIMK; d++) ad[d] = pack2(a[d], a[d]);
    float s = 0.f;
    for (int p = 0; p < NN / 2; p++) {
        ull l = abs2(add2(ad[0], sb[0][p]));
        #pragma unroll
        for (int d = 1; d < DIMK; d++)
            l = add2(l, abs2(add2(ad[d], sb[d][p])));
        float2 lf = unpack(l);
        s += __expf(-lf.x) + __expf(-lf.y);
    }
    g_feats[(size_t)m * NN + tid] = s;
}

// ---------------- final dot: partial over f-chunks, then reduce ----------------
__global__ void final_part_k(const float* __restrict__ fc_w) {
    int tid = threadIdx.x;                 // 256 (n-pairs)
    int base = blockIdx.x * FPERC;
    ull s2 = 0ULL;
    const ull* fb = reinterpret_cast<const ull*>(g_flat);
    #pragma unroll 4
    for (int r = 0; r < FPERC; r++) {
        int f = base + r;
        float w = __ldg(fc_w + f);
        ffma2(s2, __ldg(fb + (size_t)f * (NN / 2) + tid), pack2(w, w));
    }
    float2 v = unpack(s2);
    reinterpret_cast<float2*>(g_fpart + (size_t)blockIdx.x * NN)[tid] = v;
}

__global__ void final_red_k(const int* __restrict__ condition, const float* __restrict__ emb,
                            const float* __restrict__ cond_w, const float* __restrict__ cond_b,
                            const float* __restrict__ fc_w, const float* __restrict__ fc_b,
                            float* __restrict__ out) {
    int n = threadIdx.x;                   // 512
    float s = fc_b[0];
    for (int b = 0; b < FCH; b++) s += g_fpart[(size_t)b * NN + n];
    for (int m = 0; m < NUMK; m++) s += g_feats[(size_t)m * NN + n] * fc_w[FLAT + m];
    float e = emb[condition[n]];
    for (int i = 0; i < 50; i++) s += (e * cond_w[i] + cond_b[i]) * fc_w[FLAT + NUMK + i];
    out[n] = s;
}

// ---------------- launch ----------------
extern "C" void kernel_launch(void* const* d_in, const int* in_sizes, int n_in,
                              void* d_out, int out_size) {
    const float* ecg       = (const float*)d_in[0];
    const int*   condition = (const int*)  d_in[1];
    const float* w1        = (const float*)d_in[2];
    const float* b1        = (const float*)d_in[3];
    const float* u1        = (const float*)d_in[4];
    const float* w2        = (const float*)d_in[5];
    const float* b2        = (const float*)d_in[6];
    const float* u2        = (const float*)d_in[7];
    const float* w3        = (const float*)d_in[8];
    const float* b3        = (const float*)d_in[9];
    const float* u3        = (const float*)d_in[10];
    const float* emb       = (const float*)d_in[11];
    const float* cond_w    = (const float*)d_in[12];
    const float* cond_b    = (const float*)d_in[13];
    const float* mb_w      = (const float*)d_in[14];
    const float* fc_w      = (const float*)d_in[15];
    const float* fc_b      = (const float*)d_in[16];
    float* out = (float*)d_out;

    sigma_k<<<3, 256>>>(w1, u1, w2, u2, w3, u3);
    wprep_k<<<(1152 * C3 + 255) / 256, 256>>>(w1, w2, w3);
    ecgT_k<<<(LEADS * ER * NN + 255) / 256, 256>>>(ecg);
    conv1_k<<<dim3(T1 / 2, C1 / 8), 256>>>(b1);
    conv2_k<<<dim3((T2 + 1) / 2, C2 / 8), 256>>>(b2);
    conv3_k<<<dim3((T3 + 1) / 2, C3 / 8), 256>>>(b3);
    gemm_k<<<dim3((ACTW + GJT - 1) / GJT, GKS), 128>>>(mb_w);
    kreduce_k<<<(ACTW * NN + 255) / 256, 256>>>();
    mbfeat_k<<<NUMK, NN>>>();
    final_part_k<<<FCH, 256>>>(fc_w);
    final_red_k<<<1, NN>>>(condition, emb, cond_w, cond_b, fc_w, fc_b, out);
}

// round 13
// speedup vs baseline: 1.2073x; 1.0242x over previous
#include <cuda_runtime.h>
#include <cuda_bf16.h>
#include <math.h>

// ---------------- problem constants ----------------
#define NN      512
#define LIN     640
#define LEADS   3
#define T1      322
#define T2      161
#define T3      79
#define C1      64
#define C2      128
#define C3      256
#define ER      648     // ecgT padded rows (pad 4 each side)
#define X1R     336     // x1 padded rows (valid p=3..324)
#define X2R     168     // x2 padded rows (valid p=2..162)
#define FLAT    20224
#define NUMK    100
#define DIMK    5
#define ACTW    500
#define GKS     8
#define GKC     2528    // 20224/8
#define FCH     64
#define FPERC   316     // 64*316 = 20224
#define AST     40      // A smem stride (bf16 elems), 80B: 16B-aligned rows
#define BST     136     // B smem stride (bf16 elems), 272B

// ---------------- device scratch ----------------
__device__ float g_inv_sigma[3];
__device__ float g_w1t[15 * C1];                 // (ik, oc) fp32 for conv1
__device__ __nv_bfloat16 g_w2mh[C2 * 448],  g_w2ml[C2 * 448];    // [oc][ic*7+k]
__device__ __nv_bfloat16 g_w3mh[C3 * 1152], g_w3ml[C3 * 1152];   // [oc][ic*9+k]
__device__ __nv_bfloat16 g_amh[512 * FLAT], g_aml[512 * FLAT];   // [j][f], rows 500..511 zero
__device__ float g_ecgT[LEADS * ER * NN];        // [lead][p][n]
__device__ __nv_bfloat16 g_x1h[C1 * X1R * NN], g_x1l[C1 * X1R * NN];
__device__ __nv_bfloat16 g_x2h[C2 * X2R * NN], g_x2l[C2 * X2R * NN];
__device__ float g_flat[FLAT * NN];              // [f][n] fp32 (final dot)
__device__ __nv_bfloat16 g_flath[FLAT * NN], g_flatl[FLAT * NN];
__device__ float g_act_part[GKS * ACTW * NN];
__device__ float g_act[ACTW * NN];
__device__ float g_feats[NUMK * NN];
__device__ float g_fpart[FCH * NN];

typedef unsigned long long ull;

__device__ __forceinline__ void ffma2(ull& d, const ull a, const ull b) {
    asm("fma.rn.f32x2 %0, %1, %2, %0;" : "+l"(d) : "l"(a), "l"(b));
}
__device__ __forceinline__ ull add2(const ull a, const ull b) {
    ull d; asm("add.rn.f32x2 %0, %1, %2;" : "=l"(d) : "l"(a), "l"(b)); return d;
}
__device__ __forceinline__ ull abs2(const ull a) { return a & 0x7FFFFFFF7FFFFFFFULL; }
__device__ __forceinline__ ull pack2(float x, float y) {
    ull u; asm("mov.b64 %0, {%1,%2};" : "=l"(u) : "f"(x), "f"(y)); return u;
}
__device__ __forceinline__ float2 unpack(ull u) {
    float2 f; asm("mov.b64 {%0,%1}, %2;" : "=f"(f.x), "=f"(f.y) : "l"(u)); return f;
}
__device__ __forceinline__ float leaky(float x) { return x >= 0.f ? x : 0.2f * x; }
__device__ __forceinline__ void split(float v, __nv_bfloat16& h, __nv_bfloat16& l) {
    h = __float2bfloat16(v);
    l = __float2bfloat16(v - __bfloat162float(h));
}
__device__ __forceinline__ void mma_bf16(float* c, const unsigned* a, const unsigned* b) {
    asm volatile("mma.sync.aligned.m16n8k16.row.col.f32.bf16.bf16.f32 "
        "{%0,%1,%2,%3}, {%4,%5,%6,%7}, {%8,%9}, {%0,%1,%2,%3};"
        : "+f"(c[0]), "+f"(c[1]), "+f"(c[2]), "+f"(c[3])
        : "r"(a[0]), "r"(a[1]), "r"(a[2]), "r"(a[3]), "r"(b[0]), "r"(b[1]));
}
__device__ __forceinline__ void ldsm4(unsigned* r, unsigned addr) {
    asm volatile("ldmatrix.sync.aligned.m8n8.x4.shared.b16 {%0,%1,%2,%3}, [%4];"
        : "=r"(r[0]), "=r"(r[1]), "=r"(r[2]), "=r"(r[3]) : "r"(addr));
}
__device__ __forceinline__ void ldsm4t(unsigned* r, unsigned addr) {
    asm volatile("ldmatrix.sync.aligned.m8n8.x4.trans.shared.b16 {%0,%1,%2,%3}, [%4];"
        : "=r"(r[0]), "=r"(r[1]), "=r"(r[2]), "=r"(r[3]) : "r"(addr));
}
__device__ __forceinline__ unsigned s2u(const void* p) {
    return (unsigned)__cvta_generic_to_shared(p);
}

// ---------------- spectral norm ----------------
__global__ void sigma_k(const float* __restrict__ w1, const float* __restrict__ u1,
                        const float* __restrict__ w2, const float* __restrict__ u2,
                        const float* __restrict__ w3, const float* __restrict__ u3) {
    const float* W; const float* U; int O, IK;
    if (blockIdx.x == 0)      { W = w1; U = u1; O = C1; IK = 15;   }
    else if (blockIdx.x == 1) { W = w2; U = u2; O = C2; IK = 448;  }
    else                      { W = w3; U = u3; O = C3; IK = 1152; }

    __shared__ float sv[1152];
    __shared__ float red[256];
    int tid = threadIdx.x;

    float local = 0.f;
    for (int j = tid; j < IK; j += 256) {
        float v = 0.f;
        for (int i = 0; i < O; i++) v += W[i * IK + j] * U[i];
        sv[j] = v;
        local += v * v;
    }
    red[tid] = local; __syncthreads();
    for (int s = 128; s > 0; s >>= 1) { if (tid < s) red[tid] += red[tid + s]; __syncthreads(); }
    float vscale = 1.f / (sqrtf(red[0]) + 1e-12f);
    __syncthreads();
    for (int j = tid; j < IK; j += 256) sv[j] *= vscale;
    __syncthreads();

    float local2 = 0.f;
    for (int i = tid; i < O; i += 256) {
        float t = 0.f;
        for (int j = 0; j < IK; j++) t += W[i * IK + j] * sv[j];
        local2 += t * t;
    }
    red[tid] = local2; __syncthreads();
    for (int s = 128; s > 0; s >>= 1) { if (tid < s) red[tid] += red[tid + s]; __syncthreads(); }
    if (tid == 0) {
        float nt = red[0];
        float sigma = nt / (sqrtf(nt) + 1e-12f);
        g_inv_sigma[blockIdx.x] = 1.f / sigma;
    }
}

// ---------------- weight prep: fp32 conv1 weights + bf16 hi/lo for MMA ----------------
__global__ void wprep_k(const float* __restrict__ w1, const float* __restrict__ w2,
                        const float* __restrict__ w3) {
    int idx = blockIdx.x * 256 + threadIdx.x;
    if (idx < C3 * 1152) {
        float v = w3[idx] * g_inv_sigma[2];
        split(v, g_w3mh[idx], g_w3ml[idx]);
    }
    if (idx < C2 * 448) {
        float v = w2[idx] * g_inv_sigma[1];
        split(v, g_w2mh[idx], g_w2ml[idx]);
    }
    if (idx < 15 * C1) {
        int oc = idx % C1, r = idx / C1;
        g_w1t[idx] = w1[oc * 15 + r] * g_inv_sigma[0];
    }
}

// ---------------- mb_w transpose to [j][f] bf16 hi/lo ----------------
__global__ void gprep_k(const float* __restrict__ mbw) {
    size_t idx = (size_t)blockIdx.x * 256 + threadIdx.x;
    if (idx >= (size_t)ACTW * FLAT) return;
    int j = (int)(idx / FLAT), f = (int)(idx % FLAT);
    float v = mbw[(size_t)f * ACTW + j];
    split(v, g_amh[idx], g_aml[idx]);
}

// ---------------- transpose ecg(N,L,3) -> ecgT[lead][p][n] ----------------
__global__ void ecgT_k(const float* __restrict__ ecg) {
    int idx = blockIdx.x * 256 + threadIdx.x;
    if (idx >= LEADS * ER * NN) return;
    int n = idx & (NN - 1);
    int rem = idx >> 9;
    int p = rem % ER;
    int lead = rem / ER;
    int t = p - 4;
    g_ecgT[idx] = (t >= 0 && t < LIN) ? ecg[(size_t)n * (LIN * LEADS) + t * LEADS + lead] : 0.f;
}

// ---------------- conv1 (scalar FFMA2, small): ecgT -> x1 hi/lo bf16 ----------------
__global__ __launch_bounds__(256, 4) void conv1_k(const float* __restrict__ b1) {
    __shared__ __align__(16) ull sw[15 * 8];
    int tid = threadIdx.x;
    int t0 = blockIdx.x * 2;
    int oc0 = blockIdx.y * 8;
    for (int i = tid; i < 15 * 8; i += 256) {
        int j = i & 7, r = i >> 3;
        float w = g_w1t[r * C1 + oc0 + j];
        sw[i] = pack2(w, w);
    }
    ull acc[8][2];
    #pragma unroll
    for (int j = 0; j < 8; j++) { float b = b1[oc0 + j]; acc[j][0] = acc[j][1] = pack2(b, b); }
    __syncthreads();
    #pragma unroll
    for (int lead = 0; lead < LEADS; lead++) {
        const ull* xp = reinterpret_cast<const ull*>(g_ecgT + ((size_t)lead * ER + 2 * t0) * NN) + tid;
        ull in[7];
        #pragma unroll
        for (int r = 0; r < 7; r++) in[r] = __ldg(xp + r * (NN / 2));
        #pragma unroll
        for (int k = 0; k < 5; k++) {
            const ulonglong2* wp = reinterpret_cast<const ulonglong2*>(&sw[(lead * 5 + k) * 8]);
            ulonglong2 wa = wp[0], wb = wp[1], wc = wp[2], wd = wp[3];
            ffma2(acc[0][0], in[k], wa.x); ffma2(acc[0][1], in[k + 2], wa.x);
            ffma2(acc[1][0], in[k], wa.y); ffma2(acc[1][1], in[k + 2], wa.y);
            ffma2(acc[2][0], in[k], wb.x); ffma2(acc[2][1], in[k + 2], wb.x);
            ffma2(acc[3][0], in[k], wb.y); ffma2(acc[3][1], in[k + 2], wb.y);
            ffma2(acc[4][0], in[k], wc.x); ffma2(acc[4][1], in[k + 2], wc.x);
            ffma2(acc[5][0], in[k], wc.y); ffma2(acc[5][1], in[k + 2], wc.y);
            ffma2(acc[6][0], in[k], wd.x); ffma2(acc[6][1], in[k + 2], wd.x);
            ffma2(acc[7][0], in[k], wd.y); ffma2(acc[7][1], in[k + 2], wd.y);
        }
    }
    #pragma unroll
    for (int j = 0; j < 8; j++) {
        int oc = oc0 + j;
        float2 v0 = unpack(acc[j][0]);
        float2 v1 = unpack(acc[j][1]);
        v0.x = leaky(v0.x); v0.y = leaky(v0.y);
        v1.x = leaky(v1.x); v1.y = leaky(v1.y);
        size_t base = ((size_t)oc * X1R + (t0 + 3)) * NN;
        __nv_bfloat162* oh = reinterpret_cast<__nv_bfloat162*>(g_x1h + base);
        __nv_bfloat162* ol = reinterpret_cast<__nv_bfloat162*>(g_x1l + base);
        __nv_bfloat162 h, l;
        split(v0.x, h.x, l.x); split(v0.y, h.y, l.y);
        oh[tid] = h; ol[tid] = l;
        split(v1.x, h.x, l.x); split(v1.y, h.y, l.y);
        oh[NN / 2 + tid] = h; ol[NN / 2 + tid] = l;
    }
}

// ---------------- unified bf16-split MMA kernel ----------------
// MODE 0: conv2  D=leaky(W2·x1+b)  -> x2 hi/lo      (M=128, K=448,  kdiv=7)
// MODE 1: conv3  D=leaky(W3·x2+b)  -> flat fp32+h/l (M=256, K=1152, kdiv=9)
// MODE 2: gemm   D=mbW^T·flat      -> act_part[kz]  (M=512, K split 8x2528)
template<int MODE>
__global__ __launch_bounds__(256) void mma_k(const float* __restrict__ bias) {
    constexpr int KTOT = (MODE == 0) ? 448 : (MODE == 1 ? 1152 : GKC);
    constexpr int KDIV = (MODE == 0) ? 7 : 9;
    constexpr int ASTRIDE = (MODE == 0) ? 448 : (MODE == 1 ? 1152 : FLAT);
    constexpr int XROWS = (MODE == 0) ? X1R : X2R;

    __shared__ __align__(16) __nv_bfloat16 sAh[64 * AST], sAl[64 * AST];
    __shared__ __align__(16) __nv_bfloat16 sBh[32 * BST], sBl[32 * BST];

    const __nv_bfloat16 *Agh, *Agl, *Xh, *Xl;
    if constexpr (MODE == 0)      { Agh = g_w2mh; Agl = g_w2ml; Xh = g_x1h;   Xl = g_x1l;   }
    else if constexpr (MODE == 1) { Agh = g_w3mh; Agl = g_w3ml; Xh = g_x2h;   Xl = g_x2l;   }
    else                          { Agh = g_amh;  Agl = g_aml;  Xh = g_flath; Xl = g_flatl; }

    int tid = threadIdx.x, lane = tid & 31, w = tid >> 5;
    int m0 = blockIdx.x * 64;
    int t  = blockIdx.y;                 // t for convs, kz for gemm
    int n0 = blockIdx.z * 128;
    int kbase = (MODE == 2) ? t * GKC : 0;
    int wm = (w >> 2) * 32, wn = (w & 3) * 32;
    int lk = lane & 15, lg = lane >> 4;

    float acc[2][4][4];
    #pragma unroll
    for (int a = 0; a < 2; a++)
        #pragma unroll
        for (int b = 0; b < 4; b++)
            #pragma unroll
            for (int c = 0; c < 4; c++) acc[a][b][c] = 0.f;

    for (int ks = 0; ks < KTOT; ks += 32) {
        int k0 = kbase + ks;
        __syncthreads();
        // stage A: 64 rows x 32 k (hi+lo)
        for (int i = tid; i < 512; i += 256) {
            int hl = i >> 8, ii = i & 255;
            int row = ii >> 2, ch = (ii & 3) << 3;
            uint4 v = *reinterpret_cast<const uint4*>(
                (hl ? Agl : Agh) + (size_t)(m0 + row) * ASTRIDE + k0 + ch);
            *reinterpret_cast<uint4*>((hl ? sAl : sAh) + row * AST + ch) = v;
        }
        // stage B: 32 k-rows x 128 n (hi+lo), with row gather
        for (int i = tid; i < 1024; i += 256) {
            int hl = i >> 9, ii = i & 511;
            int rr = ii >> 4, ch = (ii & 15) << 3;
            int r = k0 + rr;
            size_t grow;
            if constexpr (MODE == 2) grow = (size_t)r * NN;
            else {
                int ic = r / KDIV, kk = r - ic * KDIV;
                grow = (size_t)(ic * XROWS + 2 * t + kk) * NN;
            }
            uint4 v = *reinterpret_cast<const uint4*>((hl ? Xl : Xh) + grow + n0 + ch);
            *reinterpret_cast<uint4*>((hl ? sBl : sBh) + rr * BST + ch) = v;
        }
        __syncthreads();
        #pragma unroll
        for (int kk = 0; kk < 32; kk += 16) {
            unsigned Ah[2][4], Al[2][4], Bh[2][4], Bl[2][4];
            #pragma unroll
            for (int mi = 0; mi < 2; mi++) {
                int arow = wm + mi * 16 + lk;
                ldsm4(Ah[mi], s2u(sAh + arow * AST + kk + lg * 8));
                ldsm4(Al[mi], s2u(sAl + arow * AST + kk + lg * 8));
            }
            #pragma unroll
            for (int ng = 0; ng < 2; ng++) {
                int bcol = wn + ng * 16 + lg * 8;
                ldsm4t(Bh[ng], s2u(sBh + (kk + lk) * BST + bcol));
                ldsm4t(Bl[ng], s2u(sBl + (kk + lk) * BST + bcol));
            }
            #pragma unroll
            for (int mi = 0; mi < 2; mi++)
                #pragma unroll
                for (int nf = 0; nf < 4; nf++) {
                    const unsigned* bh = &Bh[nf >> 1][(nf & 1) * 2];
                    const unsigned* bl = &Bl[nf >> 1][(nf & 1) * 2];
                    mma_bf16(acc[mi][nf], Ah[mi], bh);
                    mma_bf16(acc[mi][nf], Ah[mi], bl);
                    mma_bf16(acc[mi][nf], Al[mi], bh);
                }
        }
    }
    // epilogue
    #pragma unroll
    for (int mi = 0; mi < 2; mi++)
        #pragma unroll
        for (int nf = 0; nf < 4; nf++)
            #pragma unroll
            for (int half = 0; half < 2; half++) {
                int row = wm + mi * 16 + (lane >> 2) + half * 8;
                int col = wn + nf * 8 + ((lane & 3) << 1);
                float v0 = acc[mi][nf][2 * half], v1 = acc[mi][nf][2 * half + 1];
                if constexpr (MODE == 2) {
                    int j = m0 + row;
                    if (j < ACTW)
                        *reinterpret_cast<float2*>(
                            g_act_part + ((size_t)t * ACTW + j) * NN + n0 + col) = make_float2(v0, v1);
                } else {
                    int oc = m0 + row;
                    float b = bias[oc];
                    v0 = leaky(v0 + b); v1 = leaky(v1 + b);
                    __nv_bfloat162 h, l;
                    split(v0, h.x, l.x); split(v1, h.y, l.y);
                    if constexpr (MODE == 0) {
                        size_t o = ((size_t)oc * X2R + t + 2) * NN + n0 + col;
                        *reinterpret_cast<__nv_bfloat162*>(g_x2h + o) = h;
                        *reinterpret_cast<__nv_bfloat162*>(g_x2l + o) = l;
                    } else {
                        size_t o = ((size_t)oc * T3 + t) * NN + n0 + col;
                        *reinterpret_cast<float2*>(g_flat + o) = make_float2(v0, v1);
                        *reinterpret_cast<__nv_bfloat162*>(g_flath + o) = h;
                        *reinterpret_cast<__nv_bfloat162*>(g_flatl + o) = l;
                    }
                }
            }
}

__global__ void kreduce_k() {
    int idx = blockIdx.x * 256 + threadIdx.x;
    if (idx < ACTW * NN) {
        float s = 0.f;
        #pragma unroll
        for (int z = 0; z < GKS; z++) s += g_act_part[(size_t)z * (ACTW * NN) + idx];
        g_act[idx] = s;
    }
}

// ---------------- minibatch discrimination ----------------
__global__ void mbfeat_k() {
    __shared__ ull sb[DIMK][NN / 2];
    int m = blockIdx.x, tid = threadIdx.x;
    float a[DIMK];
    #pragma unroll
    for (int d = 0; d < DIMK; d++)
        a[d] = g_act[(size_t)(m * DIMK + d) * NN + tid];
    for (int i = tid; i < DIMK * (NN / 2); i += NN) {
        int d = i / (NN / 2), p = i % (NN / 2);
        const float* src = g_act + (size_t)(m * DIMK + d) * NN + 2 * p;
        sb[d][p] = pack2(-src[0], -src[1]);
    }
    __syncthreads();
    ull ad[DIMK];
    #pragma unroll
    for (int d = 0; d < DIMK; d++) ad[d] = pack2(a[d], a[d]);
    float s = 0.f;
    for (int p = 0; p < NN / 2; p++) {
        ull l = abs2(add2(ad[0], sb[0][p]));
        #pragma unroll
        for (int d = 1; d < DIMK; d++)
            l = add2(l, abs2(add2(ad[d], sb[d][p])));
        float2 lf = unpack(l);
        s += __expf(-lf.x) + __expf(-lf.y);
    }
    g_feats[(size_t)m * NN + tid] = s;
}

// ---------------- final dot ----------------
__global__ void final_part_k(const float* __restrict__ fc_w) {
    int tid = threadIdx.x;                 // 256 (n-pairs)
    int base = blockIdx.x * FPERC;
    ull s2 = 0ULL;
    const ull* fb = reinterpret_cast<const ull*>(g_flat);
    #pragma unroll 4
    for (int r = 0; r < FPERC; r++) {
        int f = base + r;
        float w = __ldg(fc_w + f);
        ffma2(s2, __ldg(fb + (size_t)f * (NN / 2) + tid), pack2(w, w));
    }
    float2 v = unpack(s2);
    reinterpret_cast<float2*>(g_fpart + (size_t)blockIdx.x * NN)[tid] = v;
}

__global__ void final_red_k(const int* __restrict__ condition, const float* __restrict__ emb,
                            const float* __restrict__ cond_w, const float* __restrict__ cond_b,
                            const float* __restrict__ fc_w, const float* __restrict__ fc_b,
                            float* __restrict__ out) {
    int n = threadIdx.x;
    float s = fc_b[0];
    for (int b = 0; b < FCH; b++) s += g_fpart[(size_t)b * NN + n];
    for (int m = 0; m < NUMK; m++) s += g_feats[(size_t)m * NN + n] * fc_w[FLAT + m];
    float e = emb[condition[n]];
    for (int i = 0; i < 50; i++) s += (e * cond_w[i] + cond_b[i]) * fc_w[FLAT + NUMK + i];
    out[n] = s;
}

// ---------------- launch ----------------
extern "C" void kernel_launch(void* const* d_in, const int* in_sizes, int n_in,
                              void* d_out, int out_size) {
    const float* ecg       = (const float*)d_in[0];
    const int*   condition = (const int*)  d_in[1];
    const float* w1        = (const float*)d_in[2];
    const float* b1        = (const float*)d_in[3];
    const float* u1        = (const float*)d_in[4];
    const float* w2        = (const float*)d_in[5];
    const float* b2        = (const float*)d_in[6];
    const float* u2        = (const float*)d_in[7];
    const float* w3        = (const float*)d_in[8];
    const float* b3        = (const float*)d_in[9];
    const float* u3        = (const float*)d_in[10];
    const float* emb       = (const float*)d_in[11];
    const float* cond_w    = (const float*)d_in[12];
    const float* cond_b    = (const float*)d_in[13];
    const float* mb_w      = (const float*)d_in[14];
    const float* fc_w      = (const float*)d_in[15];
    const float* fc_b      = (const float*)d_in[16];
    float* out = (float*)d_out;

    sigma_k<<<3, 256>>>(w1, u1, w2, u2, w3, u3);
    wprep_k<<<(C3 * 1152 + 255) / 256, 256>>>(w1, w2, w3);
    gprep_k<<<(int)(((size_t)ACTW * FLAT + 255) / 256), 256>>>(mb_w);
    ecgT_k<<<(LEADS * ER * NN + 255) / 256, 256>>>(ecg);
    conv1_k<<<dim3(T1 / 2, C1 / 8), 256>>>(b1);
    mma_k<0><<<dim3(C2 / 64, T2, 4), 256>>>(b2);
    mma_k<1><<<dim3(C3 / 64, T3, 4), 256>>>(b3);
    mma_k<2><<<dim3(512 / 64, GKS, 4), 256>>>(nullptr);
    kreduce_k<<<(ACTW * NN + 255) / 256, 256>>>();
    mbfeat_k<<<NUMK, NN>>>();
    final_part_k<<<FCH, 256>>>(fc_w);
    final_red_k<<<1, NN>>>(condition, emb, cond_w, cond_b, fc_w, fc_b, out);
}

// round 14
// speedup vs baseline: 2.1870x; 1.8115x over previous
#include <cuda_runtime.h>
#include <cuda_bf16.h>
#include <math.h>

// ---------------- problem constants ----------------
#define NN      512
#define LIN     640
#define LEADS   3
#define T1      322
#define T2      161
#define T3      79
#define C1      64
#define C2      128
#define C3      256
#define ER      648
#define X1R     336
#define X2R     168
#define FLAT    20224
#define NUMK    100
#define DIMK    5
#define ACTW    500
#define GKS     8
#define GKC     2528    // 20224/8
#define FCH     64
#define FPERC   316
#define AST     40      // A smem stride (bf16), 80B rows
#define BST     136     // B smem stride (bf16), 272B rows

// ---------------- device scratch ----------------
__device__ float g_inv_sigma[3];
__device__ float g_w1t[15 * C1];
__device__ __nv_bfloat16 g_w2mh[C2 * 448],  g_w2ml[C2 * 448];
__device__ __nv_bfloat16 g_w3mh[C3 * 1152], g_w3ml[C3 * 1152];
__device__ __nv_bfloat16 g_amh[512 * FLAT], g_aml[512 * FLAT];   // rows 500..511 stay zero
__device__ float g_ecgT[LEADS * ER * NN];
__device__ __nv_bfloat16 g_x1h[C1 * X1R * NN], g_x1l[C1 * X1R * NN];
__device__ __nv_bfloat16 g_x2h[C2 * X2R * NN], g_x2l[C2 * X2R * NN];
__device__ float g_flat[FLAT * NN];
__device__ __nv_bfloat16 g_flath[FLAT * NN], g_flatl[FLAT * NN];
__device__ float g_act_part[GKS * ACTW * NN];
__device__ float g_act[ACTW * NN];
__device__ float g_feats[NUMK * NN];
__device__ float g_fpart[FCH * NN];

typedef unsigned long long ull;

__device__ __forceinline__ void ffma2(ull& d, const ull a, const ull b) {
    asm("fma.rn.f32x2 %0, %1, %2, %0;" : "+l"(d) : "l"(a), "l"(b));
}
__device__ __forceinline__ ull add2(const ull a, const ull b) {
    ull d; asm("add.rn.f32x2 %0, %1, %2;" : "=l"(d) : "l"(a), "l"(b)); return d;
}
__device__ __forceinline__ ull abs2(const ull a) { return a & 0x7FFFFFFF7FFFFFFFULL; }
__device__ __forceinline__ ull pack2(float x, float y) {
    ull u; asm("mov.b64 %0, {%1,%2};" : "=l"(u) : "f"(x), "f"(y)); return u;
}
__device__ __forceinline__ float2 unpack(ull u) {
    float2 f; asm("mov.b64 {%0,%1}, %2;" : "=f"(f.x), "=f"(f.y) : "l"(u)); return f;
}
__device__ __forceinline__ float leaky(float x) { return x >= 0.f ? x : 0.2f * x; }
__device__ __forceinline__ void split(float v, __nv_bfloat16& h, __nv_bfloat16& l) {
    h = __float2bfloat16(v);
    l = __float2bfloat16(v - __bfloat162float(h));
}
__device__ __forceinline__ void mma_bf16(float* c, const unsigned* a, const unsigned* b) {
    asm volatile("mma.sync.aligned.m16n8k16.row.col.f32.bf16.bf16.f32 "
        "{%0,%1,%2,%3}, {%4,%5,%6,%7}, {%8,%9}, {%0,%1,%2,%3};"
        : "+f"(c[0]), "+f"(c[1]), "+f"(c[2]), "+f"(c[3])
        : "r"(a[0]), "r"(a[1]), "r"(a[2]), "r"(a[3]), "r"(b[0]), "r"(b[1]));
}
__device__ __forceinline__ void ldsm4(unsigned* r, unsigned addr) {
    asm volatile("ldmatrix.sync.aligned.m8n8.x4.shared.b16 {%0,%1,%2,%3}, [%4];"
        : "=r"(r[0]), "=r"(r[1]), "=r"(r[2]), "=r"(r[3]) : "r"(addr));
}
__device__ __forceinline__ void ldsm4t(unsigned* r, unsigned addr) {
    asm volatile("ldmatrix.sync.aligned.m8n8.x4.trans.shared.b16 {%0,%1,%2,%3}, [%4];"
        : "=r"(r[0]), "=r"(r[1]), "=r"(r[2]), "=r"(r[3]) : "r"(addr));
}
__device__ __forceinline__ unsigned s2u(const void* p) {
    return (unsigned)__cvta_generic_to_shared(p);
}
__device__ __forceinline__ void cpa16(unsigned smem, const void* g) {
    asm volatile("cp.async.ca.shared.global [%0], [%1], 16;" :: "r"(smem), "l"(g));
}
__device__ __forceinline__ void cpa_commit() { asm volatile("cp.async.commit_group;"); }
template<int N> __device__ __forceinline__ void cpa_wait() {
    asm volatile("cp.async.wait_group %0;" :: "n"(N));
}

// ---------------- spectral norm ----------------
__global__ void sigma_k(const float* __restrict__ w1, const float* __restrict__ u1,
                        const float* __restrict__ w2, const float* __restrict__ u2,
                        const float* __restrict__ w3, const float* __restrict__ u3) {
    const float* W; const float* U; int O, IK;
    if (blockIdx.x == 0)      { W = w1; U = u1; O = C1; IK = 15;   }
    else if (blockIdx.x == 1) { W = w2; U = u2; O = C2; IK = 448;  }
    else                      { W = w3; U = u3; O = C3; IK = 1152; }

    __shared__ float sv[1152];
    __shared__ float red[256];
    int tid = threadIdx.x;

    float local = 0.f;
    for (int j = tid; j < IK; j += 256) {
        float v = 0.f;
        for (int i = 0; i < O; i++) v += W[i * IK + j] * U[i];
        sv[j] = v;
        local += v * v;
    }
    red[tid] = local; __syncthreads();
    for (int s = 128; s > 0; s >>= 1) { if (tid < s) red[tid] += red[tid + s]; __syncthreads(); }
    float vscale = 1.f / (sqrtf(red[0]) + 1e-12f);
    __syncthreads();
    for (int j = tid; j < IK; j += 256) sv[j] *= vscale;
    __syncthreads();

    float local2 = 0.f;
    for (int i = tid; i < O; i += 256) {
        float t = 0.f;
        for (int j = 0; j < IK; j++) t += W[i * IK + j] * sv[j];
        local2 += t * t;
    }
    red[tid] = local2; __syncthreads();
    for (int s = 128; s > 0; s >>= 1) { if (tid < s) red[tid] += red[tid + s]; __syncthreads(); }
    if (tid == 0) {
        float nt = red[0];
        float sigma = nt / (sqrtf(nt) + 1e-12f);
        g_inv_sigma[blockIdx.x] = 1.f / sigma;
    }
}

// ---------------- weight prep ----------------
__global__ void wprep_k(const float* __restrict__ w1, const float* __restrict__ w2,
                        const float* __restrict__ w3) {
    int idx = blockIdx.x * 256 + threadIdx.x;
    if (idx < C3 * 1152) {
        float v = w3[idx] * g_inv_sigma[2];
        split(v, g_w3mh[idx], g_w3ml[idx]);
    }
    if (idx < C2 * 448) {
        float v = w2[idx] * g_inv_sigma[1];
        split(v, g_w2mh[idx], g_w2ml[idx]);
    }
    if (idx < 15 * C1) {
        int oc = idx % C1, r = idx / C1;
        g_w1t[idx] = w1[oc * 15 + r] * g_inv_sigma[0];
    }
}

// ---------------- mb_w transpose (coalesced 32x32 tiles): [f][j] -> [j][f] hi/lo ----------------
__global__ void gprep_k(const float* __restrict__ mbw) {
    __shared__ float tile[32][33];
    int tx = threadIdx.x & 31, ty = threadIdx.x >> 5;      // 32 x 8
    int f0 = blockIdx.x * 32, j0 = blockIdx.y * 32;
    #pragma unroll
    for (int i = ty; i < 32; i += 8) {
        int f = f0 + i, j = j0 + tx;
        tile[i][tx] = (j < ACTW) ? mbw[(size_t)f * ACTW + j] : 0.f;
    }
    __syncthreads();
    #pragma unroll
    for (int i = ty; i < 32; i += 8) {
        int j = j0 + i, f = f0 + tx;
        if (j < ACTW) {
            float v = tile[tx][i];
            __nv_bfloat16 h, l; split(v, h, l);
            g_amh[(size_t)j * FLAT + f] = h;
            g_aml[(size_t)j * FLAT + f] = l;
        }
    }
}

// ---------------- transpose ecg(N,L,3) -> ecgT[lead][p][n] ----------------
__global__ void ecgT_k(const float* __restrict__ ecg) {
    int idx = blockIdx.x * 256 + threadIdx.x;
    if (idx >= LEADS * ER * NN) return;
    int n = idx & (NN - 1);
    int rem = idx >> 9;
    int p = rem % ER;
    int lead = rem / ER;
    int t = p - 4;
    g_ecgT[idx] = (t >= 0 && t < LIN) ? ecg[(size_t)n * (LIN * LEADS) + t * LEADS + lead] : 0.f;
}

// ---------------- conv1 (scalar): ecgT -> x1 hi/lo bf16 ----------------
__global__ __launch_bounds__(256, 4) void conv1_k(const float* __restrict__ b1) {
    __shared__ __align__(16) ull sw[15 * 8];
    int tid = threadIdx.x;
    int t0 = blockIdx.x * 2;
    int oc0 = blockIdx.y * 8;
    for (int i = tid; i < 15 * 8; i += 256) {
        int j = i & 7, r = i >> 3;
        float w = g_w1t[r * C1 + oc0 + j];
        sw[i] = pack2(w, w);
    }
    ull acc[8][2];
    #pragma unroll
    for (int j = 0; j < 8; j++) { float b = b1[oc0 + j]; acc[j][0] = acc[j][1] = pack2(b, b); }
    __syncthreads();
    #pragma unroll
    for (int lead = 0; lead < LEADS; lead++) {
        const ull* xp = reinterpret_cast<const ull*>(g_ecgT + ((size_t)lead * ER + 2 * t0) * NN) + tid;
        ull in[7];
        #pragma unroll
        for (int r = 0; r < 7; r++) in[r] = __ldg(xp + r * (NN / 2));
        #pragma unroll
        for (int k = 0; k < 5; k++) {
            const ulonglong2* wp = reinterpret_cast<const ulonglong2*>(&sw[(lead * 5 + k) * 8]);
            ulonglong2 wa = wp[0], wb = wp[1], wc = wp[2], wd = wp[3];
            ffma2(acc[0][0], in[k], wa.x); ffma2(acc[0][1], in[k + 2], wa.x);
            ffma2(acc[1][0], in[k], wa.y); ffma2(acc[1][1], in[k + 2], wa.y);
            ffma2(acc[2][0], in[k], wb.x); ffma2(acc[2][1], in[k + 2], wb.x);
            ffma2(acc[3][0], in[k], wb.y); ffma2(acc[3][1], in[k + 2], wb.y);
            ffma2(acc[4][0], in[k], wc.x); ffma2(acc[4][1], in[k + 2], wc.x);
            ffma2(acc[5][0], in[k], wc.y); ffma2(acc[5][1], in[k + 2], wc.y);
            ffma2(acc[6][0], in[k], wd.x); ffma2(acc[6][1], in[k + 2], wd.x);
            ffma2(acc[7][0], in[k], wd.y); ffma2(acc[7][1], in[k + 2], wd.y);
        }
    }
    #pragma unroll
    for (int j = 0; j < 8; j++) {
        int oc = oc0 + j;
        float2 v0 = unpack(acc[j][0]);
        float2 v1 = unpack(acc[j][1]);
        v0.x = leaky(v0.x); v0.y = leaky(v0.y);
        v1.x = leaky(v1.x); v1.y = leaky(v1.y);
        size_t base = ((size_t)oc * X1R + (t0 + 3)) * NN;
        __nv_bfloat162* oh = reinterpret_cast<__nv_bfloat162*>(g_x1h + base);
        __nv_bfloat162* ol = reinterpret_cast<__nv_bfloat162*>(g_x1l + base);
        __nv_bfloat162 h, l;
        split(v0.x, h.x, l.x); split(v0.y, h.y, l.y);
        oh[tid] = h; ol[tid] = l;
        split(v1.x, h.x, l.x); split(v1.y, h.y, l.y);
        oh[NN / 2 + tid] = h; ol[NN / 2 + tid] = l;
    }
}

// ---------------- unified bf16-split MMA kernel, cp.async double-buffered ----------------
template<int MODE>
__global__ __launch_bounds__(256) void mma_k(const float* __restrict__ bias) {
    constexpr int KTOT = (MODE == 0) ? 448 : (MODE == 1 ? 1152 : GKC);
    constexpr int KDIV = (MODE == 0) ? 7 : 9;
    constexpr int ASTRIDE = (MODE == 0) ? 448 : (MODE == 1 ? 1152 : FLAT);
    constexpr int XROWS = (MODE == 0) ? X1R : X2R;
    constexpr int NCH = KTOT / 32;

    __shared__ __align__(16) __nv_bfloat16 sAh[2][64 * AST], sAl[2][64 * AST];
    __shared__ __align__(16) __nv_bfloat16 sBh[2][32 * BST], sBl[2][32 * BST];

    const __nv_bfloat16 *Agh, *Agl, *Xh, *Xl;
    if constexpr (MODE == 0)      { Agh = g_w2mh; Agl = g_w2ml; Xh = g_x1h;   Xl = g_x1l;   }
    else if constexpr (MODE == 1) { Agh = g_w3mh; Agl = g_w3ml; Xh = g_x2h;   Xl = g_x2l;   }
    else                          { Agh = g_amh;  Agl = g_aml;  Xh = g_flath; Xl = g_flatl; }

    int tid = threadIdx.x, lane = tid & 31, w = tid >> 5;
    int m0 = blockIdx.x * 64;
    int t  = blockIdx.y;                 // t for convs, kz for gemm
    int n0 = blockIdx.z * 128;
    int kbase = (MODE == 2) ? t * GKC : 0;
    int wm = (w >> 2) * 32, wn = (w & 3) * 32;
    int lk = lane & 15, lg = lane >> 4;

    float acc[2][4][4];
    #pragma unroll
    for (int a = 0; a < 2; a++)
        #pragma unroll
        for (int b = 0; b < 4; b++)
            #pragma unroll
            for (int c = 0; c < 4; c++) acc[a][b][c] = 0.f;

    // staging lambda-equivalent via macro-ish inline
    auto stage = [&](int buf, int k0) {
        #pragma unroll
        for (int i = tid; i < 512; i += 256) {          // A: 64 rows x 32 k, hi+lo
            int hl = i >> 8, ii = i & 255;
            int row = ii >> 2, ch = (ii & 3) << 3;
            const __nv_bfloat16* src = (hl ? Agl : Agh) + (size_t)(m0 + row) * ASTRIDE + k0 + ch;
            cpa16(s2u((hl ? sAl[buf] : sAh[buf]) + row * AST + ch), src);
        }
        #pragma unroll
        for (int i = tid; i < 1024; i += 256) {         // B: 32 rows x 128 n, hi+lo
            int hl = i >> 9, ii = i & 511;
            int rr = ii >> 4, ch = (ii & 15) << 3;
            int r = k0 + rr;
            size_t grow;
            if constexpr (MODE == 2) grow = (size_t)r * NN;
            else {
                int ic = r / KDIV, kk = r - ic * KDIV;
                grow = (size_t)(ic * XROWS + 2 * t + kk) * NN;
            }
            const __nv_bfloat16* src = (hl ? Xl : Xh) + grow + n0 + ch;
            cpa16(s2u((hl ? sBl[buf] : sBh[buf]) + rr * BST + ch), src);
        }
        cpa_commit();
    };

    stage(0, kbase);
    for (int c = 0; c < NCH; c++) {
        if (c + 1 < NCH) stage((c + 1) & 1, kbase + (c + 1) * 32);
        if (c + 1 < NCH) cpa_wait<1>(); else cpa_wait<0>();
        __syncthreads();
        int b = c & 1;
        #pragma unroll
        for (int kk = 0; kk < 32; kk += 16) {
            unsigned Ah[2][4], Al[2][4], Bh[2][4], Bl[2][4];
            #pragma unroll
            for (int mi = 0; mi < 2; mi++) {
                int arow = wm + mi * 16 + lk;
                ldsm4(Ah[mi], s2u(sAh[b] + arow * AST + kk + lg * 8));
                ldsm4(Al[mi], s2u(sAl[b] + arow * AST + kk + lg * 8));
            }
            #pragma unroll
            for (int ng = 0; ng < 2; ng++) {
                int bcol = wn + ng * 16 + lg * 8;
                ldsm4t(Bh[ng], s2u(sBh[b] + (kk + lk) * BST + bcol));
                ldsm4t(Bl[ng], s2u(sBl[b] + (kk + lk) * BST + bcol));
            }
            // term-major: spaces same-acc MMAs 8 apart
            #pragma unroll
            for (int mi = 0; mi < 2; mi++)
                #pragma unroll
                for (int nf = 0; nf < 4; nf++)
                    mma_bf16(acc[mi][nf], Ah[mi], &Bh[nf >> 1][(nf & 1) * 2]);
            #pragma unroll
            for (int mi = 0; mi < 2; mi++)
                #pragma unroll
                for (int nf = 0; nf < 4; nf++)
                    mma_bf16(acc[mi][nf], Ah[mi], &Bl[nf >> 1][(nf & 1) * 2]);
            #pragma unroll
            for (int mi = 0; mi < 2; mi++)
                #pragma unroll
                for (int nf = 0; nf < 4; nf++)
                    mma_bf16(acc[mi][nf], Al[mi], &Bh[nf >> 1][(nf & 1) * 2]);
        }
        __syncthreads();
    }
    // epilogue
    #pragma unroll
    for (int mi = 0; mi < 2; mi++)
        #pragma unroll
        for (int nf = 0; nf < 4; nf++)
            #pragma unroll
            for (int half = 0; half < 2; half++) {
                int row = wm + mi * 16 + (lane >> 2) + half * 8;
                int col = wn + nf * 8 + ((lane & 3) << 1);
                float v0 = acc[mi][nf][2 * half], v1 = acc[mi][nf][2 * half + 1];
                if constexpr (MODE == 2) {
                    int j = m0 + row;
                    if (j < ACTW)
                        *reinterpret_cast<float2*>(
                            g_act_part + ((size_t)t * ACTW + j) * NN + n0 + col) = make_float2(v0, v1);
                } else {
                    int oc = m0 + row;
                    float b = bias[oc];
                    v0 = leaky(v0 + b); v1 = leaky(v1 + b);
                    __nv_bfloat162 h, l;
                    split(v0, h.x, l.x); split(v1, h.y, l.y);
                    if constexpr (MODE == 0) {
                        size_t o = ((size_t)oc * X2R + t + 2) * NN + n0 + col;
                        *reinterpret_cast<__nv_bfloat162*>(g_x2h + o) = h;
                        *reinterpret_cast<__nv_bfloat162*>(g_x2l + o) = l;
                    } else {
                        size_t o = ((size_t)oc * T3 + t) * NN + n0 + col;
                        *reinterpret_cast<float2*>(g_flat + o) = make_float2(v0, v1);
                        *reinterpret_cast<__nv_bfloat162*>(g_flath + o) = h;
                        *reinterpret_cast<__nv_bfloat162*>(g_flatl + o) = l;
                    }
                }
            }
}

__global__ void kreduce_k() {
    int idx = blockIdx.x * 256 + threadIdx.x;
    if (idx < ACTW * NN) {
        float s = 0.f;
        #pragma unroll
        for (int z = 0; z < GKS; z++) s += g_act_part[(size_t)z * (ACTW * NN) + idx];
        g_act[idx] = s;
    }
}

// ---------------- minibatch discrimination ----------------
__global__ void mbfeat_k() {
    __shared__ ull sb[DIMK][NN / 2];
    int m = blockIdx.x, tid = threadIdx.x;
    float a[DIMK];
    #pragma unroll
    for (int d = 0; d < DIMK; d++)
        a[d] = g_act[(size_t)(m * DIMK + d) * NN + tid];
    for (int i = tid; i < DIMK * (NN / 2); i += NN) {
        int d = i / (NN / 2), p = i % (NN / 2);
        const float* src = g_act + (size_t)(m * DIMK + d) * NN + 2 * p;
        sb[d][p] = pack2(-src[0], -src[1]);
    }
    __syncthreads();
    ull ad[DIMK];
    #pragma unroll
    for (int d = 0; d < DIMK; d++) ad[d] = pack2(a[d], a[d]);
    float s = 0.f;
    for (int p = 0; p < NN / 2; p++) {
        ull l = abs2(add2(ad[0], sb[0][p]));
        #pragma unroll
        for (int d = 1; d < DIMK; d++)
            l = add2(l, abs2(add2(ad[d], sb[d][p])));
        float2 lf = unpack(l);
        s += __expf(-lf.x) + __expf(-lf.y);
    }
    g_feats[(size_t)m * NN + tid] = s;
}

// ---------------- final dot ----------------
__global__ void final_part_k(const float* __restrict__ fc_w) {
    int tid = threadIdx.x;
    int base = blockIdx.x * FPERC;
    ull s2 = 0ULL;
    const ull* fb = reinterpret_cast<const ull*>(g_flat);
    #pragma unroll 4
    for (int r = 0; r < FPERC; r++) {
        int f = base + r;
        float w = __ldg(fc_w + f);
        ffma2(s2, __ldg(fb + (size_t)f * (NN / 2) + tid), pack2(w, w));
    }
    float2 v = unpack(s2);
    reinterpret_cast<float2*>(g_fpart + (size_t)blockIdx.x * NN)[tid] = v;
}

__global__ void final_red_k(const int* __restrict__ condition, const float* __restrict__ emb,
                            const float* __restrict__ cond_w, const float* __restrict__ cond_b,
                            const float* __restrict__ fc_w, const float* __restrict__ fc_b,
                            float* __restrict__ out) {
    int n = threadIdx.x;
    float s = fc_b[0];
    for (int b = 0; b < FCH; b++) s += g_fpart[(size_t)b * NN + n];
    for (int m = 0; m < NUMK; m++) s += g_feats[(size_t)m * NN + n] * fc_w[FLAT + m];
    float e = emb[condition[n]];
    for (int i = 0; i < 50; i++) s += (e * cond_w[i] + cond_b[i]) * fc_w[FLAT + NUMK + i];
    out[n] = s;
}

// ---------------- launch ----------------
extern "C" void kernel_launch(void* const* d_in, const int* in_sizes, int n_in,
                              void* d_out, int out_size) {
    const float* ecg       = (const float*)d_in[0];
    const int*   condition = (const int*)  d_in[1];
    const float* w1        = (const float*)d_in[2];
    const float* b1        = (const float*)d_in[3];
    const float* u1        = (const float*)d_in[4];
    const float* w2        = (const float*)d_in[5];
    const float* b2        = (const float*)d_in[6];
    const float* u2        = (const float*)d_in[7];
    const float* w3        = (const float*)d_in[8];
    const float* b3        = (const float*)d_in[9];
    const float* u3        = (const float*)d_in[10];
    const float* emb       = (const float*)d_in[11];
    const float* cond_w    = (const float*)d_in[12];
    const float* cond_b    = (const float*)d_in[13];
    const float* mb_w      = (const float*)d_in[14];
    const float* fc_w      = (const float*)d_in[15];
    const float* fc_b      = (const float*)d_in[16];
    float* out = (float*)d_out;

    sigma_k<<<3, 256>>>(w1, u1, w2, u2, w3, u3);
    wprep_k<<<(C3 * 1152 + 255) / 256, 256>>>(w1, w2, w3);
    gprep_k<<<dim3(FLAT / 32, (ACTW + 31) / 32), 256>>>(mb_w);
    ecgT_k<<<(LEADS * ER * NN + 255) / 256, 256>>>(ecg);
    conv1_k<<<dim3(T1 / 2, C1 / 8), 256>>>(b1);
    mma_k<0><<<dim3(C2 / 64, T2, 4), 256>>>(b2);
    mma_k<1><<<dim3(C3 / 64, T3, 4), 256>>>(b3);
    mma_k<2><<<dim3(512 / 64, GKS, 4), 256>>>(nullptr);
    kreduce_k<<<(ACTW * NN + 255) / 256, 256>>>();
    mbfeat_k<<<NUMK, NN>>>();
    final_part_k<<<FCH, 256>>>(fc_w);
    final_red_k<<<1, NN>>>(condition, emb, cond_w, cond_b, fc_w, fc_b, out);
}

// round 15
// speedup vs baseline: 2.1982x; 1.0051x over previous
#include <cuda_runtime.h>
#include <cuda_bf16.h>
#include <math.h>

// ---------------- problem constants ----------------
#define NN      512
#define LIN     640
#define LEADS   3
#define T1      322
#define T2      161
#define T3      79
#define C1      64
#define C2      128
#define C3      256
#define ER      648
#define X1R     336
#define X2R     168
#define FLAT    20224
#define NUMK    100
#define DIMK    5
#define ACTW    500
#define GKS     8
#define GKC     2528    // 20224/8
#define FCH     64
#define FPERC   316
#define AST     40      // A smem stride (bf16), 80B rows
#define BST     136     // B smem stride (bf16), 272B rows
#define SMEM_MMA (3 * (2 * 64 * AST + 2 * 32 * BST) * 2)   // 82944 B

// ---------------- device scratch ----------------
__device__ float g_inv_sigma[3];
__device__ float g_w1t[15 * C1];
__device__ __nv_bfloat16 g_w2mh[C2 * 448],  g_w2ml[C2 * 448];
__device__ __nv_bfloat16 g_w3mh[C3 * 1152], g_w3ml[C3 * 1152];
__device__ __nv_bfloat16 g_amh[512 * FLAT], g_aml[512 * FLAT];   // rows 500..511 stay zero
__device__ float g_ecgT[LEADS * ER * NN];
__device__ __nv_bfloat16 g_x1h[C1 * X1R * NN], g_x1l[C1 * X1R * NN];
__device__ __nv_bfloat16 g_x2h[C2 * X2R * NN], g_x2l[C2 * X2R * NN];
__device__ __nv_bfloat16 g_flath[FLAT * NN], g_flatl[FLAT * NN];
__device__ float g_act_part[GKS * ACTW * NN];
__device__ float g_act[ACTW * NN];
__device__ float g_feats[NUMK * NN];
__device__ float g_fpart[FCH * NN];

typedef unsigned long long ull;

__device__ __forceinline__ void ffma2(ull& d, const ull a, const ull b) {
    asm("fma.rn.f32x2 %0, %1, %2, %0;" : "+l"(d) : "l"(a), "l"(b));
}
__device__ __forceinline__ ull add2(const ull a, const ull b) {
    ull d; asm("add.rn.f32x2 %0, %1, %2;" : "=l"(d) : "l"(a), "l"(b)); return d;
}
__device__ __forceinline__ ull abs2(const ull a) { return a & 0x7FFFFFFF7FFFFFFFULL; }
__device__ __forceinline__ ull pack2(float x, float y) {
    ull u; asm("mov.b64 %0, {%1,%2};" : "=l"(u) : "f"(x), "f"(y)); return u;
}
__device__ __forceinline__ float2 unpack(ull u) {
    float2 f; asm("mov.b64 {%0,%1}, %2;" : "=f"(f.x), "=f"(f.y) : "l"(u)); return f;
}
__device__ __forceinline__ float leaky(float x) { return x >= 0.f ? x : 0.2f * x; }
__device__ __forceinline__ void split(float v, __nv_bfloat16& h, __nv_bfloat16& l) {
    h = __float2bfloat16(v);
    l = __float2bfloat16(v - __bfloat162float(h));
}
__device__ __forceinline__ void mma_bf16(float* c, const unsigned* a, const unsigned* b) {
    asm volatile("mma.sync.aligned.m16n8k16.row.col.f32.bf16.bf16.f32 "
        "{%0,%1,%2,%3}, {%4,%5,%6,%7}, {%8,%9}, {%0,%1,%2,%3};"
        : "+f"(c[0]), "+f"(c[1]), "+f"(c[2]), "+f"(c[3])
        : "r"(a[0]), "r"(a[1]), "r"(a[2]), "r"(a[3]), "r"(b[0]), "r"(b[1]));
}
__device__ __forceinline__ void ldsm4(unsigned* r, unsigned addr) {
    asm volatile("ldmatrix.sync.aligned.m8n8.x4.shared.b16 {%0,%1,%2,%3}, [%4];"
        : "=r"(r[0]), "=r"(r[1]), "=r"(r[2]), "=r"(r[3]) : "r"(addr));
}
__device__ __forceinline__ void ldsm4t(unsigned* r, unsigned addr) {
    asm volatile("ldmatrix.sync.aligned.m8n8.x4.trans.shared.b16 {%0,%1,%2,%3}, [%4];"
        : "=r"(r[0]), "=r"(r[1]), "=r"(r[2]), "=r"(r[3]) : "r"(addr));
}
__device__ __forceinline__ unsigned s2u(const void* p) {
    return (unsigned)__cvta_generic_to_shared(p);
}
__device__ __forceinline__ void cpa16(unsigned smem, const void* g) {
    asm volatile("cp.async.ca.shared.global [%0], [%1], 16;" :: "r"(smem), "l"(g));
}
__device__ __forceinline__ void cpa_commit() { asm volatile("cp.async.commit_group;"); }
template<int N> __device__ __forceinline__ void cpa_wait() {
    asm volatile("cp.async.wait_group %0;" :: "n"(N));
}

// ---------------- spectral norm ----------------
__global__ void sigma_k(const float* __restrict__ w1, const float* __restrict__ u1,
                        const float* __restrict__ w2, const float* __restrict__ u2,
                        const float* __restrict__ w3, const float* __restrict__ u3) {
    const float* W; const float* U; int O, IK;
    if (blockIdx.x == 0)      { W = w1; U = u1; O = C1; IK = 15;   }
    else if (blockIdx.x == 1) { W = w2; U = u2; O = C2; IK = 448;  }
    else                      { W = w3; U = u3; O = C3; IK = 1152; }

    __shared__ float sv[1152];
    __shared__ float red[256];
    int tid = threadIdx.x;

    float local = 0.f;
    for (int j = tid; j < IK; j += 256) {
        float v = 0.f;
        for (int i = 0; i < O; i++) v += W[i * IK + j] * U[i];
        sv[j] = v;
        local += v * v;
    }
    red[tid] = local; __syncthreads();
    for (int s = 128; s > 0; s >>= 1) { if (tid < s) red[tid] += red[tid + s]; __syncthreads(); }
    float vscale = 1.f / (sqrtf(red[0]) + 1e-12f);
    __syncthreads();
    for (int j = tid; j < IK; j += 256) sv[j] *= vscale;
    __syncthreads();

    float local2 = 0.f;
    for (int i = tid; i < O; i += 256) {
        float t = 0.f;
        for (int j = 0; j < IK; j++) t += W[i * IK + j] * sv[j];
        local2 += t * t;
    }
    red[tid] = local2; __syncthreads();
    for (int s = 128; s > 0; s >>= 1) { if (tid < s) red[tid] += red[tid + s]; __syncthreads(); }
    if (tid == 0) {
        float nt = red[0];
        float sigma = nt / (sqrtf(nt) + 1e-12f);
        g_inv_sigma[blockIdx.x] = 1.f / sigma;
    }
}

// ---------------- weight prep ----------------
__global__ void wprep_k(const float* __restrict__ w1, const float* __restrict__ w2,
                        const float* __restrict__ w3) {
    int idx = blockIdx.x * 256 + threadIdx.x;
    if (idx < C3 * 1152) {
        float v = w3[idx] * g_inv_sigma[2];
        split(v, g_w3mh[idx], g_w3ml[idx]);
    }
    if (idx < C2 * 448) {
        float v = w2[idx] * g_inv_sigma[1];
        split(v, g_w2mh[idx], g_w2ml[idx]);
    }
    if (idx < 15 * C1) {
        int oc = idx % C1, r = idx / C1;
        g_w1t[idx] = w1[oc * 15 + r] * g_inv_sigma[0];
    }
}

// ---------------- mb_w transpose (coalesced 32x32 tiles): [f][j] -> [j][f] hi/lo ----------------
__global__ void gprep_k(const float* __restrict__ mbw) {
    __shared__ float tile[32][33];
    int tx = threadIdx.x & 31, ty = threadIdx.x >> 5;      // 32 x 8
    int f0 = blockIdx.x * 32, j0 = blockIdx.y * 32;
    #pragma unroll
    for (int i = ty; i < 32; i += 8) {
        int f = f0 + i, j = j0 + tx;
        tile[i][tx] = (j < ACTW) ? mbw[(size_t)f * ACTW + j] : 0.f;
    }
    __syncthreads();
    #pragma unroll
    for (int i = ty; i < 32; i += 8) {
        int j = j0 + i, f = f0 + tx;
        if (j < ACTW) {
            float v = tile[tx][i];
            __nv_bfloat16 h, l; split(v, h, l);
            g_amh[(size_t)j * FLAT + f] = h;
            g_aml[(size_t)j * FLAT + f] = l;
        }
    }
}

// ---------------- transpose ecg(N,L,3) -> ecgT[lead][p][n] ----------------
__global__ void ecgT_k(const float* __restrict__ ecg) {
    int idx = blockIdx.x * 256 + threadIdx.x;
    if (idx >= LEADS * ER * NN) return;
    int n = idx & (NN - 1);
    int rem = idx >> 9;
    int p = rem % ER;
    int lead = rem / ER;
    int t = p - 4;
    g_ecgT[idx] = (t >= 0 && t < LIN) ? ecg[(size_t)n * (LIN * LEADS) + t * LEADS + lead] : 0.f;
}

// ---------------- conv1 (scalar): ecgT -> x1 hi/lo bf16 ----------------
__global__ __launch_bounds__(256, 4) void conv1_k(const float* __restrict__ b1) {
    __shared__ __align__(16) ull sw[15 * 8];
    int tid = threadIdx.x;
    int t0 = blockIdx.x * 2;
    int oc0 = blockIdx.y * 8;
    for (int i = tid; i < 15 * 8; i += 256) {
        int j = i & 7, r = i >> 3;
        float w = g_w1t[r * C1 + oc0 + j];
        sw[i] = pack2(w, w);
    }
    ull acc[8][2];
    #pragma unroll
    for (int j = 0; j < 8; j++) { float b = b1[oc0 + j]; acc[j][0] = acc[j][1] = pack2(b, b); }
    __syncthreads();
    #pragma unroll
    for (int lead = 0; lead < LEADS; lead++) {
        const ull* xp = reinterpret_cast<const ull*>(g_ecgT + ((size_t)lead * ER + 2 * t0) * NN) + tid;
        ull in[7];
        #pragma unroll
        for (int r = 0; r < 7; r++) in[r] = __ldg(xp + r * (NN / 2));
        #pragma unroll
        for (int k = 0; k < 5; k++) {
            const ulonglong2* wp = reinterpret_cast<const ulonglong2*>(&sw[(lead * 5 + k) * 8]);
            ulonglong2 wa = wp[0], wb = wp[1], wc = wp[2], wd = wp[3];
            ffma2(acc[0][0], in[k], wa.x); ffma2(acc[0][1], in[k + 2], wa.x);
            ffma2(acc[1][0], in[k], wa.y); ffma2(acc[1][1], in[k + 2], wa.y);
            ffma2(acc[2][0], in[k], wb.x); ffma2(acc[2][1], in[k + 2], wb.x);
            ffma2(acc[3][0], in[k], wb.y); ffma2(acc[3][1], in[k + 2], wb.y);
            ffma2(acc[4][0], in[k], wc.x); ffma2(acc[4][1], in[k + 2], wc.x);
            ffma2(acc[5][0], in[k], wc.y); ffma2(acc[5][1], in[k + 2], wc.y);
            ffma2(acc[6][0], in[k], wd.x); ffma2(acc[6][1], in[k + 2], wd.x);
            ffma2(acc[7][0], in[k], wd.y); ffma2(acc[7][1], in[k + 2], wd.y);
        }
    }
    #pragma unroll
    for (int j = 0; j < 8; j++) {
        int oc = oc0 + j;
        float2 v0 = unpack(acc[j][0]);
        float2 v1 = unpack(acc[j][1]);
        v0.x = leaky(v0.x); v0.y = leaky(v0.y);
        v1.x = leaky(v1.x); v1.y = leaky(v1.y);
        size_t base = ((size_t)oc * X1R + (t0 + 3)) * NN;
        __nv_bfloat162* oh = reinterpret_cast<__nv_bfloat162*>(g_x1h + base);
        __nv_bfloat162* ol = reinterpret_cast<__nv_bfloat162*>(g_x1l + base);
        __nv_bfloat162 h, l;
        split(v0.x, h.x, l.x); split(v0.y, h.y, l.y);
        oh[tid] = h; ol[tid] = l;
        split(v1.x, h.x, l.x); split(v1.y, h.y, l.y);
        oh[NN / 2 + tid] = h; ol[NN / 2 + tid] = l;
    }
}

// ---------------- unified bf16-split MMA kernel, 3-stage cp.async ----------------
template<int MODE>
__global__ __launch_bounds__(256) void mma_k(const float* __restrict__ bias) {
    constexpr int KTOT = (MODE == 0) ? 448 : (MODE == 1 ? 1152 : GKC);
    constexpr int KDIV = (MODE == 0) ? 7 : 9;
    constexpr int ASTRIDE = (MODE == 0) ? 448 : (MODE == 1 ? 1152 : FLAT);
    constexpr int XROWS = (MODE == 0) ? X1R : X2R;
    constexpr int NCH = KTOT / 32;
    constexpr int ASZ = 64 * AST;          // bf16 elems per A buffer
    constexpr int BSZ = 32 * BST;

    extern __shared__ __align__(16) char dsm[];
    __nv_bfloat16* sAh = reinterpret_cast<__nv_bfloat16*>(dsm);
    __nv_bfloat16* sAl = sAh + 3 * ASZ;
    __nv_bfloat16* sBh = sAl + 3 * ASZ;
    __nv_bfloat16* sBl = sBh + 3 * BSZ;

    const __nv_bfloat16 *Agh, *Agl, *Xh, *Xl;
    if constexpr (MODE == 0)      { Agh = g_w2mh; Agl = g_w2ml; Xh = g_x1h;   Xl = g_x1l;   }
    else if constexpr (MODE == 1) { Agh = g_w3mh; Agl = g_w3ml; Xh = g_x2h;   Xl = g_x2l;   }
    else                          { Agh = g_amh;  Agl = g_aml;  Xh = g_flath; Xl = g_flatl; }

    int tid = threadIdx.x, lane = tid & 31, w = tid >> 5;
    int m0 = blockIdx.x * 64;
    int t  = blockIdx.y;                 // t for convs, kz for gemm
    int n0 = blockIdx.z * 128;
    int kbase = (MODE == 2) ? t * GKC : 0;
    int wm = (w >> 2) * 32, wn = (w & 3) * 32;
    int lk = lane & 15, lg = lane >> 4;

    float acc[2][4][4];
    #pragma unroll
    for (int a = 0; a < 2; a++)
        #pragma unroll
        for (int b = 0; b < 4; b++)
            #pragma unroll
            for (int c = 0; c < 4; c++) acc[a][b][c] = 0.f;

    auto stage = [&](int buf, int k0) {
        #pragma unroll
        for (int i = tid; i < 512; i += 256) {          // A: 64 rows x 32 k, hi+lo
            int hl = i >> 8, ii = i & 255;
            int row = ii >> 2, ch = (ii & 3) << 3;
            const __nv_bfloat16* src = (hl ? Agl : Agh) + (size_t)(m0 + row) * ASTRIDE + k0 + ch;
            cpa16(s2u((hl ? sAl : sAh) + buf * ASZ + row * AST + ch), src);
        }
        #pragma unroll
        for (int i = tid; i < 1024; i += 256) {         // B: 32 rows x 128 n, hi+lo
            int hl = i >> 9, ii = i & 511;
            int rr = ii >> 4, ch = (ii & 15) << 3;
            int r = k0 + rr;
            size_t grow;
            if constexpr (MODE == 2) grow = (size_t)r * NN;
            else {
                int ic = r / KDIV, kk = r - ic * KDIV;
                grow = (size_t)(ic * XROWS + 2 * t + kk) * NN;
            }
            const __nv_bfloat16* src = (hl ? Xl : Xh) + grow + n0 + ch;
            cpa16(s2u((hl ? sBl : sBh) + buf * BSZ + rr * BST + ch), src);
        }
        cpa_commit();
    };

    stage(0, kbase);
    stage(1, kbase + 32);
    for (int c = 0; c < NCH; c++) {
        if (c + 1 < NCH) cpa_wait<1>(); else cpa_wait<0>();
        __syncthreads();
        if (c + 2 < NCH) stage((c + 2) % 3, kbase + (c + 2) * 32);
        int b = c % 3;
        const __nv_bfloat16* Ah_s = sAh + b * ASZ;
        const __nv_bfloat16* Al_s = sAl + b * ASZ;
        const __nv_bfloat16* Bh_s = sBh + b * BSZ;
        const __nv_bfloat16* Bl_s = sBl + b * BSZ;
        #pragma unroll
        for (int kk = 0; kk < 32; kk += 16) {
            unsigned Ah[2][4], Al[2][4], Bh[2][4], Bl[2][4];
            #pragma unroll
            for (int mi = 0; mi < 2; mi++) {
                int arow = wm + mi * 16 + lk;
                ldsm4(Ah[mi], s2u(Ah_s + arow * AST + kk + lg * 8));
                ldsm4(Al[mi], s2u(Al_s + arow * AST + kk + lg * 8));
            }
            #pragma unroll
            for (int ng = 0; ng < 2; ng++) {
                int bcol = wn + ng * 16 + lg * 8;
                ldsm4t(Bh[ng], s2u(Bh_s + (kk + lk) * BST + bcol));
                ldsm4t(Bl[ng], s2u(Bl_s + (kk + lk) * BST + bcol));
            }
            #pragma unroll
            for (int mi = 0; mi < 2; mi++)
                #pragma unroll
                for (int nf = 0; nf < 4; nf++)
                    mma_bf16(acc[mi][nf], Ah[mi], &Bh[nf >> 1][(nf & 1) * 2]);
            #pragma unroll
            for (int mi = 0; mi < 2; mi++)
                #pragma unroll
                for (int nf = 0; nf < 4; nf++)
                    mma_bf16(acc[mi][nf], Ah[mi], &Bl[nf >> 1][(nf & 1) * 2]);
            #pragma unroll
            for (int mi = 0; mi < 2; mi++)
                #pragma unroll
                for (int nf = 0; nf < 4; nf++)
                    mma_bf16(acc[mi][nf], Al[mi], &Bh[nf >> 1][(nf & 1) * 2]);
        }
    }
    // epilogue
    #pragma unroll
    for (int mi = 0; mi < 2; mi++)
        #pragma unroll
        for (int nf = 0; nf < 4; nf++)
            #pragma unroll
            for (int half = 0; half < 2; half++) {
                int row = wm + mi * 16 + (lane >> 2) + half * 8;
                int col = wn + nf * 8 + ((lane & 3) << 1);
                float v0 = acc[mi][nf][2 * half], v1 = acc[mi][nf][2 * half + 1];
                if constexpr (MODE == 2) {
                    int j = m0 + row;
                    if (j < ACTW)
                        *reinterpret_cast<float2*>(
                            g_act_part + ((size_t)t * ACTW + j) * NN + n0 + col) = make_float2(v0, v1);
                } else {
                    int oc = m0 + row;
                    float b = bias[oc];
                    v0 = leaky(v0 + b); v1 = leaky(v1 + b);
                    __nv_bfloat162 h, l;
                    split(v0, h.x, l.x); split(v1, h.y, l.y);
                    if constexpr (MODE == 0) {
                        size_t o = ((size_t)oc * X2R + t + 2) * NN + n0 + col;
                        *reinterpret_cast<__nv_bfloat162*>(g_x2h + o) = h;
                        *reinterpret_cast<__nv_bfloat162*>(g_x2l + o) = l;
                    } else {
                        size_t o = ((size_t)oc * T3 + t) * NN + n0 + col;
                        *reinterpret_cast<__nv_bfloat162*>(g_flath + o) = h;
                        *reinterpret_cast<__nv_bfloat162*>(g_flatl + o) = l;
                    }
                }
            }
}

__global__ void kreduce_k() {
    int idx = blockIdx.x * 256 + threadIdx.x;
    if (idx < ACTW * NN) {
        float s = 0.f;
        #pragma unroll
        for (int z = 0; z < GKS; z++) s += g_act_part[(size_t)z * (ACTW * NN) + idx];
        g_act[idx] = s;
    }
}

// ---------------- minibatch discrimination ----------------
__global__ void mbfeat_k() {
    __shared__ ull sb[DIMK][NN / 2];
    int m = blockIdx.x, tid = threadIdx.x;
    float a[DIMK];
    #pragma unroll
    for (int d = 0; d < DIMK; d++)
        a[d] = g_act[(size_t)(m * DIMK + d) * NN + tid];
    for (int i = tid; i < DIMK * (NN / 2); i += NN) {
        int d = i / (NN / 2), p = i % (NN / 2);
        const float* src = g_act + (size_t)(m * DIMK + d) * NN + 2 * p;
        sb[d][p] = pack2(-src[0], -src[1]);
    }
    __syncthreads();
    ull ad[DIMK];
    #pragma unroll
    for (int d = 0; d < DIMK; d++) ad[d] = pack2(a[d], a[d]);
    float s = 0.f;
    for (int p = 0; p < NN / 2; p++) {
        ull l = abs2(add2(ad[0], sb[0][p]));
        #pragma unroll
        for (int d = 1; d < DIMK; d++)
            l = add2(l, abs2(add2(ad[d], sb[d][p])));
        float2 lf = unpack(l);
        s += __expf(-lf.x) + __expf(-lf.y);
    }
    g_feats[(size_t)m * NN + tid] = s;
}

// ---------------- final dot (reads flat = h + l) ----------------
__global__ void final_part_k(const float* __restrict__ fc_w) {
    int tid = threadIdx.x;                 // 256 (n-pairs)
    int base = blockIdx.x * FPERC;
    float2 s = make_float2(0.f, 0.f);
    const __nv_bfloat162* fh = reinterpret_cast<const __nv_bfloat162*>(g_flath);
    const __nv_bfloat162* fl = reinterpret_cast<const __nv_bfloat162*>(g_flatl);
    #pragma unroll 4
    for (int r = 0; r < FPERC; r++) {
        int f = base + r;
        float w = __ldg(fc_w + f);
        __nv_bfloat162 h = fh[(size_t)f * (NN / 2) + tid];
        __nv_bfloat162 l = fl[(size_t)f * (NN / 2) + tid];
        s.x += (__bfloat162float(h.x) + __bfloat162float(l.x)) * w;
        s.y += (__bfloat162float(h.y) + __bfloat162float(l.y)) * w;
    }
    reinterpret_cast<float2*>(g_fpart + (size_t)blockIdx.x * NN)[tid] = s;
}

__global__ void final_red_k(const int* __restrict__ condition, const float* __restrict__ emb,
                            const float* __restrict__ cond_w, const float* __restrict__ cond_b,
                            const float* __restrict__ fc_w, const float* __restrict__ fc_b,
                            float* __restrict__ out) {
    int n = threadIdx.x;
    float s = fc_b[0];
    for (int b = 0; b < FCH; b++) s += g_fpart[(size_t)b * NN + n];
    for (int m = 0; m < NUMK; m++) s += g_feats[(size_t)m * NN + n] * fc_w[FLAT + m];
    float e = emb[condition[n]];
    for (int i = 0; i < 50; i++) s += (e * cond_w[i] + cond_b[i]) * fc_w[FLAT + NUMK + i];
    out[n] = s;
}

// ---------------- launch ----------------
extern "C" void kernel_launch(void* const* d_in, const int* in_sizes, int n_in,
                              void* d_out, int out_size) {
    const float* ecg       = (const float*)d_in[0];
    const int*   condition = (const int*)  d_in[1];
    const float* w1        = (const float*)d_in[2];
    const float* b1        = (const float*)d_in[3];
    const float* u1        = (const float*)d_in[4];
    const float* w2        = (const float*)d_in[5];
    const float* b2        = (const float*)d_in[6];
    const float* u2        = (const float*)d_in[7];
    const float* w3        = (const float*)d_in[8];
    const float* b3        = (const float*)d_in[9];
    const float* u3        = (const float*)d_in[10];
    const float* emb       = (const float*)d_in[11];
    const float* cond_w    = (const float*)d_in[12];
    const float* cond_b    = (const float*)d_in[13];
    const float* mb_w      = (const float*)d_in[14];
    const float* fc_w      = (const float*)d_in[15];
    const float* fc_b      = (const float*)d_in[16];
    float* out = (float*)d_out;

    cudaFuncSetAttribute(mma_k<0>, cudaFuncAttributeMaxDynamicSharedMemorySize, SMEM_MMA);
    cudaFuncSetAttribute(mma_k<1>, cudaFuncAttributeMaxDynamicSharedMemorySize, SMEM_MMA);
    cudaFuncSetAttribute(mma_k<2>, cudaFuncAttributeMaxDynamicSharedMemorySize, SMEM_MMA);

    sigma_k<<<3, 256>>>(w1, u1, w2, u2, w3, u3);
    wprep_k<<<(C3 * 1152 + 255) / 256, 256>>>(w1, w2, w3);
    gprep_k<<<dim3(FLAT / 32, (ACTW + 31) / 32), 256>>>(mb_w);
    ecgT_k<<<(LEADS * ER * NN + 255) / 256, 256>>>(ecg);
    conv1_k<<<dim3(T1 / 2, C1 / 8), 256>>>(b1);
    mma_k<0><<<dim3(C2 / 64, T2, 4), 256, SMEM_MMA>>>(b2);
    mma_k<1><<<dim3(C3 / 64, T3, 4), 256, SMEM_MMA>>>(b3);
    mma_k<2><<<dim3(512 / 64, GKS, 4), 256, SMEM_MMA>>>(nullptr);
    kreduce_k<<<(ACTW * NN + 255) / 256, 256>>>();
    mbfeat_k<<<NUMK, NN>>>();
    final_part_k<<<FCH, 256>>>(fc_w);
    final_red_k<<<1, NN>>>(condition, emb, cond_w, cond_b, fc_w, fc_b, out);
}